// round 2
// baseline (speedup 1.0000x reference)
#include <cuda_runtime.h>
#include <cstdint>

// Problem dims
#define B_  64
#define S_  512
#define I_  512
#define H_  1024
#define G_  4096          // 4*H
#define BH_ (B_*H_)       // 65536
#define OUT_ELEMS (B_*S_*H_)   // 33554432

#define NCTA 128
#define NTHR 256
#define NCH  16           // K-chunks of 64 per 1024-wide matrix

// ---------------- device scratch (static, allowed) ----------------
__device__ float  g_Wx0p[G_*I_];            // tf32-rounded, gate-permuted rows (for precompute)
__device__ float  g_b0p[G_];                // bx0+bh0, permuted (folded into G0)
__device__ float  g_b1p[G_];                // bx1+bh1, permuted
__device__ float4 g_A0[(size_t)NCTA*NCH*512];  // Wh0 fragment-major (16MB)
__device__ float4 g_A1[(size_t)NCTA*NCH*512];  // Wx1
__device__ float4 g_A2[(size_t)NCTA*NCH*512];  // Wh1
__device__ float  g_G0[(size_t)S_*B_*G_];   // x-path preactivations [t][b][prow] (512MB)
__device__ float4 g_h0F[2][16384];          // h0 fragment-major, double buffered (256KB each)
__device__ float4 g_h1F[2][16384];          // h1 fragment-major
__device__ unsigned g_barCount;
__device__ volatile unsigned g_barGen;

// ---------------- helpers ----------------
__device__ __forceinline__ float f2tf_f(float f) {
    uint32_t r;
    asm("cvt.rna.tf32.f32 %0, %1;" : "=r"(r) : "f"(f));
    return __uint_as_float(r);
}

__device__ __forceinline__ void mma_tf32(float* d,
                                         float4 a, float2 b) {
    asm volatile(
        "mma.sync.aligned.m16n8k8.row.col.f32.tf32.tf32.f32 "
        "{%0,%1,%2,%3}, {%4,%5,%6,%7}, {%8,%9}, {%0,%1,%2,%3};\n"
        : "+f"(d[0]), "+f"(d[1]), "+f"(d[2]), "+f"(d[3])
        : "r"(__float_as_uint(a.x)), "r"(__float_as_uint(a.y)),
          "r"(__float_as_uint(a.z)), "r"(__float_as_uint(a.w)),
          "r"(__float_as_uint(b.x)), "r"(__float_as_uint(b.y)));
}

__device__ __forceinline__ float sigmoidf_(float x) { return 1.0f / (1.0f + expf(-x)); }

__device__ __forceinline__ void cpa16(uint32_t dst, const void* src) {
    asm volatile("cp.async.cg.shared.global [%0], [%1], 16;\n" :: "r"(dst), "l"(src));
}
__device__ __forceinline__ void cp_commit() { asm volatile("cp.async.commit_group;\n"); }
__device__ __forceinline__ void cp_wait1() { asm volatile("cp.async.wait_group 1;\n"); }
__device__ __forceinline__ void cp_wait0() { asm volatile("cp.async.wait_group 0;\n"); }

// grid barrier (all NCTA CTAs co-resident)
__device__ __forceinline__ void gsync() {
    __syncthreads();
    if (threadIdx.x == 0) {
        unsigned gen = g_barGen;
        __threadfence();
        if (atomicAdd(&g_barCount, 1u) == NCTA - 1) {
            g_barCount = 0;
            __threadfence();
            g_barGen = gen + 1;
        } else {
            while (g_barGen == gen) { }
            __threadfence();
        }
    }
    __syncthreads();
}

// Row permutation: prow = (u/8)*32 + q*8 + (u%8); CTA c owns units [8c,8c+8),
// prows [32c,32c+32): local row r: gate q = r>>3, unit v = r&7.

// ---------------- convert: natural Wx0 + biases ----------------
__global__ void __launch_bounds__(256) convert_nat(
    const float* __restrict__ Wx0, const float* __restrict__ bx0, const float* __restrict__ bh0,
    const float* __restrict__ bx1, const float* __restrict__ bh1)
{
    const int total = G_ * I_;
    for (int i = blockIdx.x * blockDim.x + threadIdx.x; i < total;
         i += gridDim.x * blockDim.x) {
        int prow = i / I_;
        int k    = i - prow * I_;
        int u    = ((prow >> 5) << 3) + (prow & 7);
        int q    = (prow >> 3) & 3;
        int orig = q * H_ + u;
        g_Wx0p[i] = f2tf_f(Wx0[(size_t)orig * I_ + k]);
        if (k == 0) {
            g_b0p[prow] = bx0[orig] + bh0[orig];
            g_b1p[prow] = bx1[orig] + bh1[orig];
        }
    }
}

// ---------------- convert: fragment-major recurrent weights ----------------
// idx = c<<13 | ch<<9 | wm<<8 | kk<<5 | lane ; f4 = {W[o0][k],W[o1][k],W[o0][k+4],W[o1][k+4]}
__global__ void __launch_bounds__(256) convert_frag(
    const float* __restrict__ Wh0, const float* __restrict__ Wx1, const float* __restrict__ Wh1)
{
    const int total = NCTA * NCH * 512;   // 1048576
    for (int idx = blockIdx.x * blockDim.x + threadIdx.x; idx < total;
         idx += gridDim.x * blockDim.x) {
        int lane = idx & 31;
        int kk   = (idx >> 5) & 7;
        int wm   = (idx >> 8) & 1;
        int ch   = (idx >> 9) & 15;
        int c    = idx >> 13;
        int g4 = lane >> 2, t4 = lane & 3;
        int p0 = wm * 16 + g4;
        int q0 = p0 >> 3, v = p0 & 7;
        int o0 = q0 * H_ + c * 8 + v;   // original row; o1 = o0 + H_
        int k  = ch * 64 + kk * 8 + t4;
        size_t r0 = (size_t)o0 * H_ + k;
        size_t r1 = r0 + (size_t)H_ * H_;   // (o0+H_)*H_ + k
        g_A0[idx] = make_float4(f2tf_f(Wh0[r0]), f2tf_f(Wh0[r1]),
                                f2tf_f(Wh0[r0 + 4]), f2tf_f(Wh0[r1 + 4]));
        g_A1[idx] = make_float4(f2tf_f(Wx1[r0]), f2tf_f(Wx1[r1]),
                                f2tf_f(Wx1[r0 + 4]), f2tf_f(Wx1[r1 + 4]));
        g_A2[idx] = make_float4(f2tf_f(Wh1[r0]), f2tf_f(Wh1[r1]),
                                f2tf_f(Wh1[r0 + 4]), f2tf_f(Wh1[r1 + 4]));
    }
}

// ---------------- init (every replay) ----------------
__global__ void __launch_bounds__(256) init_kernel() {
    int i = blockIdx.x * blockDim.x + threadIdx.x;
    if (i < 16384) {
        g_h0F[0][i] = make_float4(0.f, 0.f, 0.f, 0.f);
        g_h1F[0][i] = make_float4(0.f, 0.f, 0.f, 0.f);
    }
    if (i == 0) { g_barCount = 0; g_barGen = 0; }
}

// ---------------- x-path precompute: G0[t][b][prow] = x@Wx0p^T + b0p ----------------
__global__ void __launch_bounds__(256) precompute_kernel(const float* __restrict__ x)
{
    __shared__ float As[128][20];
    __shared__ float Bs[64][20];

    const int tid  = threadIdx.x;
    const int w    = tid >> 5;
    const int lane = tid & 31;
    const int wM   = w >> 2;
    const int wN   = w & 3;
    const int mBase = blockIdx.y * 128;
    const int nBase = blockIdx.x * 64;
    const int g4 = lane >> 2;
    const int t4 = lane & 3;

    float acc[4][2][4];
#pragma unroll
    for (int mt = 0; mt < 4; mt++)
#pragma unroll
        for (int nt = 0; nt < 2; nt++)
#pragma unroll
            for (int e = 0; e < 4; e++) acc[mt][nt][e] = 0.0f;

    for (int kc = 0; kc < I_; kc += 16) {
#pragma unroll
        for (int it = 0; it < 2; it++) {
            int i  = tid + it * 256;
            int r  = i >> 2;
            int c4 = (i & 3) * 4;
            int m  = mBase + r;
            int tt = m >> 6;
            int bb = m & 63;
            float4 v = *(const float4*)(x + ((size_t)bb * S_ + tt) * I_ + kc + c4);
            As[r][c4 + 0] = f2tf_f(v.x); As[r][c4 + 1] = f2tf_f(v.y);
            As[r][c4 + 2] = f2tf_f(v.z); As[r][c4 + 3] = f2tf_f(v.w);
        }
        {
            int r  = tid >> 2;
            int c4 = (tid & 3) * 4;
            float4 v = *(const float4*)(g_Wx0p + (size_t)(nBase + r) * I_ + kc + c4);
            Bs[r][c4 + 0] = v.x; Bs[r][c4 + 1] = v.y;
            Bs[r][c4 + 2] = v.z; Bs[r][c4 + 3] = v.w;
        }
        __syncthreads();

#pragma unroll
        for (int kk = 0; kk < 2; kk++) {
            int k = kk * 8;
            float2 bf[2];
#pragma unroll
            for (int nt = 0; nt < 2; nt++) {
                int n = wN * 16 + nt * 8 + g4;
                bf[nt] = make_float2(Bs[n][k + t4], Bs[n][k + t4 + 4]);
            }
#pragma unroll
            for (int mt = 0; mt < 4; mt++) {
                int r = wM * 64 + mt * 16 + g4;
                float4 af = make_float4(As[r][k + t4], As[r + 8][k + t4],
                                        As[r][k + t4 + 4], As[r + 8][k + t4 + 4]);
#pragma unroll
                for (int nt = 0; nt < 2; nt++)
                    mma_tf32(acc[mt][nt], af, bf[nt]);
            }
        }
        __syncthreads();
    }

#pragma unroll
    for (int mt = 0; mt < 4; mt++) {
        int r0 = mBase + wM * 64 + mt * 16 + g4;
        int r1 = r0 + 8;
#pragma unroll
        for (int nt = 0; nt < 2; nt++) {
            int n0 = nBase + wN * 16 + nt * 8 + t4 * 2;
            int n1 = n0 + 1;
            g_G0[(size_t)r0 * G_ + n0] = acc[mt][nt][0] + g_b0p[n0];
            g_G0[(size_t)r0 * G_ + n1] = acc[mt][nt][1] + g_b0p[n1];
            g_G0[(size_t)r1 * G_ + n0] = acc[mt][nt][2] + g_b0p[n0];
            g_G0[(size_t)r1 * G_ + n1] = acc[mt][nt][3] + g_b0p[n1];
        }
    }
}

// ---------------- persistent recurrent kernel ----------------
// smem layout (dynamic):
//   [0,24576)          : A stages, 3 x 512 float4
//   [24576,98304)      : B stages, 3 x 3072 float2 (padded: 256 groups x 12 f2)
//   [98304,107008)     : gates 32 x 68 float
//   [107008,107136)    : bias1 slice 32 float
#define SM_A   0
#define SM_B   24576
#define SM_GS  98304
#define SM_BI  107008
#define SM_TOT 107136

struct StageSrc { const float4* a; const float4* b; };

__device__ __forceinline__ void stage_chunk(char* sm, int stg, StageSrc s, int tid)
{
    uint32_t aBase = (uint32_t)__cvta_generic_to_shared(sm + SM_A + stg * 8192);
    uint32_t bBase = (uint32_t)__cvta_generic_to_shared(sm + SM_B + stg * 24576);
    cpa16(aBase + (uint32_t)tid * 16,        s.a + tid);
    cpa16(aBase + (uint32_t)(tid + 256) * 16, s.a + tid + 256);
#pragma unroll
    for (int it = 0; it < 4; it++) {
        int s4  = tid + it * 256;         // f4 index into 1024-f4 source chunk
        int grp = s4 >> 2;                // t4-group (8 f2 = 4 f4)
        int off = s4 & 3;
        cpa16(bBase + (uint32_t)(grp * 96 + off * 16), s.b + s4);
    }
    cp_commit();
}

__global__ void __launch_bounds__(NTHR, 1) lstm_persist(float* __restrict__ out)
{
    extern __shared__ char sm[];
    float* Gs = (float*)(sm + SM_GS);
    float* sB = (float*)(sm + SM_BI);

    const int c    = blockIdx.x;
    const int tid  = threadIdx.x;
    const int w    = tid >> 5;
    const int lane = tid & 31;
    const int wm   = w >> 2;     // 0..1 : prow half
    const int wb   = w & 3;      // 0..3 : batch group of 16
    const int g4   = lane >> 2;
    const int t4   = lane & 3;

    if (tid < 32) sB[tid] = g_b1p[c * 32 + tid];
    __syncthreads();

    float c0r[2] = {0.f, 0.f};
    float c1r[2] = {0.f, 0.f};

    for (int t = 0; t < S_; t++) {
        const float4* h0r = g_h0F[t & 1];
        float*        h0w = (float*)g_h0F[(t + 1) & 1];
        const float4* h0n = g_h0F[(t + 1) & 1];   // layer1 reads new h0
        const float4* h1r = g_h1F[t & 1];
        float*        h1w = (float*)g_h1F[(t + 1) & 1];

        // ================= LAYER 0 : 16 chunks (Wh0 x h0_prev) =================
        {
            float acc[2][4];
#pragma unroll
            for (int bt = 0; bt < 2; bt++)
#pragma unroll
                for (int e = 0; e < 4; e++) acc[bt][e] = 0.f;

            const float4* aB = g_A0 + (size_t)c * NCH * 512;
            StageSrc s0 = { aB,            h0r };
            StageSrc s1 = { aB + 512,      h0r + 1024 };
            stage_chunk(sm, 0, s0, tid);
            stage_chunk(sm, 1, s1, tid);

            for (int ch = 0; ch < NCH; ch++) {
                if (ch + 1 < NCH) cp_wait1(); else cp_wait0();
                __syncthreads();
                if (ch + 2 < NCH) {
                    StageSrc sn = { aB + (size_t)(ch + 2) * 512, h0r + (size_t)(ch + 2) * 1024 };
                    stage_chunk(sm, (ch + 2) % 3, sn, tid);
                }
                int stg = ch % 3;
                const float4* As_ = (const float4*)(sm + SM_A + stg * 8192);
                const char*   Bb  = sm + SM_B + stg * 24576;
#pragma unroll
                for (int kk = 0; kk < 8; kk++) {
                    float4 af = As_[(wm * 8 + kk) * 32 + lane];
                    float2 b0f = *(const float2*)(Bb + (((kk * 8 + wb * 2    ) * 4 + t4) * 96) + g4 * 8);
                    float2 b1f = *(const float2*)(Bb + (((kk * 8 + wb * 2 + 1) * 4 + t4) * 96) + g4 * 8);
                    mma_tf32(acc[0], af, b0f);
                    mma_tf32(acc[1], af, b1f);
                }
            }

            // gates -> smem
            int r0 = wm * 16 + g4;
#pragma unroll
            for (int bt = 0; bt < 2; bt++) {
                int col = wb * 16 + bt * 8 + 2 * t4;
                Gs[r0 * 68 + col]       = acc[bt][0];
                Gs[r0 * 68 + col + 1]   = acc[bt][1];
                Gs[(r0 + 8) * 68 + col]     = acc[bt][2];
                Gs[(r0 + 8) * 68 + col + 1] = acc[bt][3];
            }
            __syncthreads();

            // LSTM cell for layer 0
#pragma unroll
            for (int it = 0; it < 2; it++) {
                int cell = tid + it * 256;
                int v = cell & 7, b = cell >> 3;
                float gi = Gs[v * 68 + b];
                float gf = Gs[(8 + v) * 68 + b];
                float go = Gs[(16 + v) * 68 + b];
                float gg = Gs[(24 + v) * 68 + b];
                size_t gbase = ((size_t)t * B_ + b) * G_ + c * 32;
                gi += g_G0[gbase + v];
                gf += g_G0[gbase + 8 + v];
                go += g_G0[gbase + 16 + v];
                gg += g_G0[gbase + 24 + v];
                float cn = sigmoidf_(gf) * c0r[it] + sigmoidf_(gi) * tanhf(gg);
                float hn = sigmoidf_(go) * tanhf(cn);
                c0r[it] = cn;
                int fidx = ((c * 256 + ((b >> 3) * 4 + (v & 3)) * 8 + (b & 7)) << 1) + (v >> 2);
                h0w[fidx] = f2tf_f(hn);
                if (t == S_ - 1) {
                    int u = c * 8 + v;
                    out[(size_t)OUT_ELEMS + (size_t)b * H_ + u]             = hn;  // h_n[0]
                    out[(size_t)OUT_ELEMS + 2ull * BH_ + (size_t)b * H_ + u] = cn; // c_n[0]
                }
            }
        }
        gsync();

        // ================= LAYER 1 : 32 chunks (Wx1 x h0_new | Wh1 x h1_prev) =================
        {
            float acc[2][4];
#pragma unroll
            for (int bt = 0; bt < 2; bt++)
#pragma unroll
                for (int e = 0; e < 4; e++) acc[bt][e] = 0.f;

            const float4* aX = g_A1 + (size_t)c * NCH * 512;
            const float4* aH = g_A2 + (size_t)c * NCH * 512;
            const int NC1 = 32;
            auto src_of = [&](int ch) -> StageSrc {
                StageSrc s;
                if (ch < 16) { s.a = aX + (size_t)ch * 512;        s.b = h0n + (size_t)ch * 1024; }
                else         { s.a = aH + (size_t)(ch - 16) * 512; s.b = h1r + (size_t)(ch - 16) * 1024; }
                return s;
            };
            stage_chunk(sm, 0, src_of(0), tid);
            stage_chunk(sm, 1, src_of(1), tid);

            for (int ch = 0; ch < NC1; ch++) {
                if (ch + 1 < NC1) cp_wait1(); else cp_wait0();
                __syncthreads();
                if (ch + 2 < NC1) stage_chunk(sm, (ch + 2) % 3, src_of(ch + 2), tid);
                int stg = ch % 3;
                const float4* As_ = (const float4*)(sm + SM_A + stg * 8192);
                const char*   Bb  = sm + SM_B + stg * 24576;
#pragma unroll
                for (int kk = 0; kk < 8; kk++) {
                    float4 af = As_[(wm * 8 + kk) * 32 + lane];
                    float2 b0f = *(const float2*)(Bb + (((kk * 8 + wb * 2    ) * 4 + t4) * 96) + g4 * 8);
                    float2 b1f = *(const float2*)(Bb + (((kk * 8 + wb * 2 + 1) * 4 + t4) * 96) + g4 * 8);
                    mma_tf32(acc[0], af, b0f);
                    mma_tf32(acc[1], af, b1f);
                }
            }

            int r0 = wm * 16 + g4;
#pragma unroll
            for (int bt = 0; bt < 2; bt++) {
                int col = wb * 16 + bt * 8 + 2 * t4;
                Gs[r0 * 68 + col]       = acc[bt][0];
                Gs[r0 * 68 + col + 1]   = acc[bt][1];
                Gs[(r0 + 8) * 68 + col]     = acc[bt][2];
                Gs[(r0 + 8) * 68 + col + 1] = acc[bt][3];
            }
            __syncthreads();

#pragma unroll
            for (int it = 0; it < 2; it++) {
                int cell = tid + it * 256;
                int v = cell & 7, b = cell >> 3;
                float gi = Gs[v * 68 + b]        + sB[v];
                float gf = Gs[(8 + v) * 68 + b]  + sB[8 + v];
                float go = Gs[(16 + v) * 68 + b] + sB[16 + v];
                float gg = Gs[(24 + v) * 68 + b] + sB[24 + v];
                float cn = sigmoidf_(gf) * c1r[it] + sigmoidf_(gi) * tanhf(gg);
                float hn = sigmoidf_(go) * tanhf(cn);
                c1r[it] = cn;
                int u = c * 8 + v;
                out[((size_t)b * S_ + t) * H_ + u] = hn;
                int fidx = ((c * 256 + ((b >> 3) * 4 + (v & 3)) * 8 + (b & 7)) << 1) + (v >> 2);
                h1w[fidx] = f2tf_f(hn);
                if (t == S_ - 1) {
                    out[(size_t)OUT_ELEMS + 1ull * BH_ + (size_t)b * H_ + u] = hn; // h_n[1]
                    out[(size_t)OUT_ELEMS + 3ull * BH_ + (size_t)b * H_ + u] = cn; // c_n[1]
                }
            }
        }
        gsync();
    }
}

// ---------------- launch ----------------
extern "C" void kernel_launch(void* const* d_in, const int* in_sizes, int n_in,
                              void* d_out, int out_size)
{
    const float* x   = (const float*)d_in[0];
    const float* Wx0 = (const float*)d_in[1];
    const float* Wh0 = (const float*)d_in[2];
    const float* bx0 = (const float*)d_in[3];
    const float* bh0 = (const float*)d_in[4];
    const float* Wx1 = (const float*)d_in[5];
    const float* Wh1 = (const float*)d_in[6];
    const float* bx1 = (const float*)d_in[7];
    const float* bh1 = (const float*)d_in[8];
    float* out = (float*)d_out;

    static bool attr_done = false;
    if (!attr_done) {
        cudaFuncSetAttribute(lstm_persist,
                             cudaFuncAttributeMaxDynamicSharedMemorySize, SM_TOT);
        attr_done = true;
    }

    convert_nat<<<2048, 256>>>(Wx0, bx0, bh0, bx1, bh1);
    convert_frag<<<4096, 256>>>(Wh0, Wx1, Wh1);
    init_kernel<<<64, 256>>>();
    precompute_kernel<<<dim3(G_ / 64, (S_ * B_) / 128), 256>>>(x);
    lstm_persist<<<NCTA, NTHR, SM_TOT>>>(out);
}

// round 3
// speedup vs baseline: 1.2168x; 1.2168x over previous
#include <cuda_runtime.h>
#include <cstdint>

// Problem dims
#define B_  64
#define S_  512
#define I_  512
#define H_  1024
#define G_  4096          // 4*H
#define BH_ (B_*H_)       // 65536
#define OUT_ELEMS (B_*S_*H_)   // 33554432

#define NCTA 128
#define NTHR 256
#define NCH  16           // K-chunks of 64 per 1024-wide matrix

// ---------------- device scratch (static, allowed) ----------------
__device__ float  g_Wx0p[G_*I_];            // tf32-rounded, gate-permuted rows (for precompute)
__device__ float  g_b0p[G_];                // bx0+bh0, permuted (folded into G0)
__device__ float  g_b1p[G_];                // bx1+bh1, permuted
__device__ float4 g_A0[(size_t)NCTA*NCH*512];  // Wh0 fragment-major (16MB) — pinned to SMEM
__device__ float4 g_A1[(size_t)NCTA*NCH*512];  // Wx1
__device__ float4 g_A2[(size_t)NCTA*NCH*512];  // Wh1
__device__ float  g_G0[(size_t)S_*B_*G_];   // x-path preactivations [t][b][prow] (512MB)
__device__ float4 g_h0F[2][16384];          // h0 fragment-major, double buffered
__device__ float4 g_h1F[2][16384];          // h1 fragment-major
__device__ unsigned g_barCount;
__device__ volatile unsigned g_barGen;

// ---------------- helpers ----------------
__device__ __forceinline__ float f2tf_f(float f) {
    uint32_t r;
    asm("cvt.rna.tf32.f32 %0, %1;" : "=r"(r) : "f"(f));
    return __uint_as_float(r);
}

__device__ __forceinline__ void mma_tf32(float* d, float4 a, float2 b) {
    asm volatile(
        "mma.sync.aligned.m16n8k8.row.col.f32.tf32.tf32.f32 "
        "{%0,%1,%2,%3}, {%4,%5,%6,%7}, {%8,%9}, {%0,%1,%2,%3};\n"
        : "+f"(d[0]), "+f"(d[1]), "+f"(d[2]), "+f"(d[3])
        : "r"(__float_as_uint(a.x)), "r"(__float_as_uint(a.y)),
          "r"(__float_as_uint(a.z)), "r"(__float_as_uint(a.w)),
          "r"(__float_as_uint(b.x)), "r"(__float_as_uint(b.y)));
}

__device__ __forceinline__ float sigmoidf_(float x) { return 1.0f / (1.0f + expf(-x)); }

__device__ __forceinline__ void cpa16(uint32_t dst, const void* src) {
    asm volatile("cp.async.cg.shared.global [%0], [%1], 16;\n" :: "r"(dst), "l"(src));
}
__device__ __forceinline__ void cp_commit() { asm volatile("cp.async.commit_group;\n"); }
__device__ __forceinline__ void cp_wait1() { asm volatile("cp.async.wait_group 1;\n"); }
__device__ __forceinline__ void cp_wait0() { asm volatile("cp.async.wait_group 0;\n"); }

// grid barrier (all NCTA CTAs co-resident)
__device__ __forceinline__ void gsync() {
    __syncthreads();
    if (threadIdx.x == 0) {
        unsigned gen = g_barGen;
        __threadfence();
        if (atomicAdd(&g_barCount, 1u) == NCTA - 1) {
            g_barCount = 0;
            __threadfence();
            g_barGen = gen + 1;
        } else {
            while (g_barGen == gen) { }
            __threadfence();
        }
    }
    __syncthreads();
}

// Row permutation: prow = (u/8)*32 + q*8 + (u%8); CTA c owns units [8c,8c+8).

// ---------------- convert: natural Wx0 + biases ----------------
__global__ void __launch_bounds__(256) convert_nat(
    const float* __restrict__ Wx0, const float* __restrict__ bx0, const float* __restrict__ bh0,
    const float* __restrict__ bx1, const float* __restrict__ bh1)
{
    const int total = G_ * I_;
    for (int i = blockIdx.x * blockDim.x + threadIdx.x; i < total;
         i += gridDim.x * blockDim.x) {
        int prow = i / I_;
        int k    = i - prow * I_;
        int u    = ((prow >> 5) << 3) + (prow & 7);
        int q    = (prow >> 3) & 3;
        int orig = q * H_ + u;
        g_Wx0p[i] = f2tf_f(Wx0[(size_t)orig * I_ + k]);
        if (k == 0) {
            g_b0p[prow] = bx0[orig] + bh0[orig];
            g_b1p[prow] = bx1[orig] + bh1[orig];
        }
    }
}

// ---------------- convert: fragment-major recurrent weights ----------------
__global__ void __launch_bounds__(256) convert_frag(
    const float* __restrict__ Wh0, const float* __restrict__ Wx1, const float* __restrict__ Wh1)
{
    const int total = NCTA * NCH * 512;
    for (int idx = blockIdx.x * blockDim.x + threadIdx.x; idx < total;
         idx += gridDim.x * blockDim.x) {
        int lane = idx & 31;
        int kk   = (idx >> 5) & 7;
        int wm   = (idx >> 8) & 1;
        int ch   = (idx >> 9) & 15;
        int c    = idx >> 13;
        int g4 = lane >> 2, t4 = lane & 3;
        int p0 = wm * 16 + g4;
        int q0 = p0 >> 3, v = p0 & 7;
        int o0 = q0 * H_ + c * 8 + v;
        int k  = ch * 64 + kk * 8 + t4;
        size_t r0 = (size_t)o0 * H_ + k;
        size_t r1 = r0 + (size_t)H_ * H_;
        g_A0[idx] = make_float4(f2tf_f(Wh0[r0]), f2tf_f(Wh0[r1]),
                                f2tf_f(Wh0[r0 + 4]), f2tf_f(Wh0[r1 + 4]));
        g_A1[idx] = make_float4(f2tf_f(Wx1[r0]), f2tf_f(Wx1[r1]),
                                f2tf_f(Wx1[r0 + 4]), f2tf_f(Wx1[r1 + 4]));
        g_A2[idx] = make_float4(f2tf_f(Wh1[r0]), f2tf_f(Wh1[r1]),
                                f2tf_f(Wh1[r0 + 4]), f2tf_f(Wh1[r1 + 4]));
    }
}

// ---------------- init (every replay): barrier state only ----------------
__global__ void init_kernel() {
    if (threadIdx.x == 0) { g_barCount = 0; g_barGen = 0; }
}

// ---------------- x-path precompute v2: G0 = x@Wx0p^T + b0p ----------------
// CTA tile 128(M) x 128(N), warps 2M x 4N, warp tile 64x32 (4m x 4n tiles)
__global__ void __launch_bounds__(256, 1) precompute_kernel(const float* __restrict__ x)
{
    __shared__ float As[128][20];
    __shared__ float Bs[128][20];

    const int tid  = threadIdx.x;
    const int w    = tid >> 5;
    const int lane = tid & 31;
    const int wM   = w >> 2;
    const int wN   = w & 3;
    const int mBase = blockIdx.y * 128;
    const int nBase = blockIdx.x * 128;
    const int g4 = lane >> 2;
    const int t4 = lane & 3;

    float acc[4][4][4];
#pragma unroll
    for (int mt = 0; mt < 4; mt++)
#pragma unroll
        for (int nt = 0; nt < 4; nt++)
#pragma unroll
            for (int e = 0; e < 4; e++) acc[mt][nt][e] = 0.0f;

    for (int kc = 0; kc < I_; kc += 16) {
#pragma unroll
        for (int it = 0; it < 2; it++) {
            int i  = tid + it * 256;
            int r  = i >> 2;
            int c4 = (i & 3) * 4;
            int m  = mBase + r;
            int tt = m >> 6;
            int bb = m & 63;
            float4 v = *(const float4*)(x + ((size_t)bb * S_ + tt) * I_ + kc + c4);
            As[r][c4 + 0] = f2tf_f(v.x); As[r][c4 + 1] = f2tf_f(v.y);
            As[r][c4 + 2] = f2tf_f(v.z); As[r][c4 + 3] = f2tf_f(v.w);
        }
#pragma unroll
        for (int it = 0; it < 2; it++) {
            int i  = tid + it * 256;
            int r  = i >> 2;
            int c4 = (i & 3) * 4;
            float4 v = *(const float4*)(g_Wx0p + (size_t)(nBase + r) * I_ + kc + c4);
            Bs[r][c4 + 0] = v.x; Bs[r][c4 + 1] = v.y;
            Bs[r][c4 + 2] = v.z; Bs[r][c4 + 3] = v.w;
        }
        __syncthreads();

#pragma unroll
        for (int kk = 0; kk < 2; kk++) {
            int k = kk * 8;
            float2 bf[4];
#pragma unroll
            for (int nt = 0; nt < 4; nt++) {
                int n = wN * 32 + nt * 8 + g4;
                bf[nt] = make_float2(Bs[n][k + t4], Bs[n][k + t4 + 4]);
            }
#pragma unroll
            for (int mt = 0; mt < 4; mt++) {
                int r = wM * 64 + mt * 16 + g4;
                float4 af = make_float4(As[r][k + t4], As[r + 8][k + t4],
                                        As[r][k + t4 + 4], As[r + 8][k + t4 + 4]);
#pragma unroll
                for (int nt = 0; nt < 4; nt++)
                    mma_tf32(acc[mt][nt], af, bf[nt]);
            }
        }
        __syncthreads();
    }

#pragma unroll
    for (int mt = 0; mt < 4; mt++) {
        int r0 = mBase + wM * 64 + mt * 16 + g4;
        int r1 = r0 + 8;
#pragma unroll
        for (int nt = 0; nt < 4; nt++) {
            int n0 = nBase + wN * 32 + nt * 8 + t4 * 2;
            float2 bv = *(const float2*)(g_b0p + n0);
            *(float2*)(g_G0 + (size_t)r0 * G_ + n0) =
                make_float2(acc[mt][nt][0] + bv.x, acc[mt][nt][1] + bv.y);
            *(float2*)(g_G0 + (size_t)r1 * G_ + n0) =
                make_float2(acc[mt][nt][2] + bv.x, acc[mt][nt][3] + bv.y);
        }
    }
}

// ---------------- persistent recurrent kernel (fused interval) ----------------
// smem layout (dynamic):
//   [0,131072)         : pinned Wh0 fragments (16 chunks x 512 float4)
//   [131072,155648)    : A stages, 3 x 512 float4   (overlaid: Gs0/Gs1 post-loop)
//   [155648,229376)    : B stages, 3 x 3072 float2 (96B-padded groups)
//   [229376,229504)    : bias1 slice (32 floats)
#define SM_W0  0
#define SM_A   131072
#define SM_B   155648
#define SM_BI  229376
#define SM_TOT 229504

struct StageSrc { const float4* a; const float4* b; };

__device__ __forceinline__ void stage_chunk(char* sm, int stg, StageSrc s, int tid)
{
    uint32_t aBase = (uint32_t)__cvta_generic_to_shared(sm + SM_A + stg * 8192);
    uint32_t bBase = (uint32_t)__cvta_generic_to_shared(sm + SM_B + stg * 24576);
    cpa16(aBase + (uint32_t)tid * 16,         s.a + tid);
    cpa16(aBase + (uint32_t)(tid + 256) * 16, s.a + tid + 256);
#pragma unroll
    for (int it = 0; it < 4; it++) {
        int s4  = tid + it * 256;
        int grp = s4 >> 2;
        int off = s4 & 3;
        cpa16(bBase + (uint32_t)(grp * 96 + off * 16), s.b + s4);
    }
    cp_commit();
}

__global__ void __launch_bounds__(NTHR, 1) lstm_persist(float* __restrict__ out)
{
    extern __shared__ char sm[];
    float* sB = (float*)(sm + SM_BI);

    const int c    = blockIdx.x;
    const int tid  = threadIdx.x;
    const int w    = tid >> 5;
    const int lane = tid & 31;
    const int wm   = w >> 2;     // 0..1 : prow half
    const int wb   = w & 3;      // 0..3 : batch group of 16
    const int g4   = lane >> 2;
    const int t4   = lane & 3;

    if (tid < 32) sB[tid] = g_b1p[c * 32 + tid];

    // pin Wh0 fragments into SMEM (once)
    {
        uint32_t dst = (uint32_t)__cvta_generic_to_shared(sm + SM_W0);
        const float4* src = g_A0 + (size_t)c * (NCH * 512);
#pragma unroll
        for (int i = 0; i < 32; i++)
            cpa16(dst + (uint32_t)(tid + i * 256) * 16, src + tid + i * 256);
        cp_commit(); cp_wait0();
    }
    __syncthreads();

    float c0r[2] = {0.f, 0.f};
    float c1r[2] = {0.f, 0.f};

    // preamble: h0[0] from G0[0] (h=0), zero h1[-1] buffer fragments
    {
        float* h0w0 = (float*)g_h0F[0];
        float* h1w0 = (float*)g_h1F[0];
#pragma unroll
        for (int it = 0; it < 2; it++) {
            int cell = tid + it * 256;
            int v = cell & 7, b = cell >> 3;
            size_t gbase = (size_t)b * G_ + c * 32;
            float gi = g_G0[gbase + v];
            float go = g_G0[gbase + 16 + v];
            float gg = g_G0[gbase + 24 + v];
            float cn = sigmoidf_(gi) * tanhf(gg);
            float hn = sigmoidf_(go) * tanhf(cn);
            c0r[it] = cn;
            int fidx = ((c * 256 + ((b >> 3) * 4 + (v & 3)) * 8 + (b & 7)) << 1) + (v >> 2);
            h0w0[fidx] = f2tf_f(hn);
            h1w0[fidx] = 0.f;
        }
    }
    gsync();

    const float4* aX = g_A1 + (size_t)c * (NCH * 512);
    const float4* aH = g_A2 + (size_t)c * (NCH * 512);

    for (int t = 0; t < S_; t++) {
        const float4* bH0 = g_h0F[t & 1];          // h0[t]
        float*        wH0 = (float*)g_h0F[(t + 1) & 1];
        const float4* bH1 = g_h1F[t & 1];          // h1[t-1]
        float*        wH1 = (float*)g_h1F[(t + 1) & 1];

        float acc0[2][4], acc1[2][4];
#pragma unroll
        for (int bt = 0; bt < 2; bt++)
#pragma unroll
            for (int e = 0; e < 4; e++) { acc0[bt][e] = 0.f; acc1[bt][e] = 0.f; }

        auto src_of = [&](int ch) -> StageSrc {
            StageSrc s;
            if (ch < 16) { s.a = aX + (size_t)ch * 512;        s.b = bH0 + (size_t)ch * 1024; }
            else         { s.a = aH + (size_t)(ch - 16) * 512; s.b = bH1 + (size_t)(ch - 16) * 1024; }
            return s;
        };
        stage_chunk(sm, 0, src_of(0), tid);
        stage_chunk(sm, 1, src_of(1), tid);

        for (int ch = 0; ch < 32; ch++) {
            if (ch + 1 < 32) cp_wait1(); else cp_wait0();
            __syncthreads();
            if (ch + 2 < 32) stage_chunk(sm, (ch + 2) % 3, src_of(ch + 2), tid);
            int stg = ch % 3;
            const float4* Astr = (const float4*)(sm + SM_A + stg * 8192);
            const char*   Bb   = sm + SM_B + stg * 24576;
            if (ch < 16) {
                const float4* Apin = (const float4*)(sm + SM_W0) + ch * 512;
#pragma unroll
                for (int kk = 0; kk < 8; kk++) {
                    float2 b0f = *(const float2*)(Bb + (((kk * 8 + wb * 2    ) * 4 + t4) * 96) + g4 * 8);
                    float2 b1f = *(const float2*)(Bb + (((kk * 8 + wb * 2 + 1) * 4 + t4) * 96) + g4 * 8);
                    float4 afs = Astr[(wm * 8 + kk) * 32 + lane];
                    float4 afp = Apin[(wm * 8 + kk) * 32 + lane];
                    mma_tf32(acc1[0], afs, b0f);
                    mma_tf32(acc1[1], afs, b1f);
                    mma_tf32(acc0[0], afp, b0f);
                    mma_tf32(acc0[1], afp, b1f);
                }
            } else {
#pragma unroll
                for (int kk = 0; kk < 8; kk++) {
                    float2 b0f = *(const float2*)(Bb + (((kk * 8 + wb * 2    ) * 4 + t4) * 96) + g4 * 8);
                    float2 b1f = *(const float2*)(Bb + (((kk * 8 + wb * 2 + 1) * 4 + t4) * 96) + g4 * 8);
                    float4 afs = Astr[(wm * 8 + kk) * 32 + lane];
                    mma_tf32(acc1[0], afs, b0f);
                    mma_tf32(acc1[1], afs, b1f);
                }
            }
        }

        // gates -> smem (overlaid on A-stage area, all A consumed)
        __syncthreads();
        float* Gs0 = (float*)(sm + SM_A);
        float* Gs1 = (float*)(sm + SM_A + 8704);
        {
            int r0 = wm * 16 + g4;
#pragma unroll
            for (int bt = 0; bt < 2; bt++) {
                int col = wb * 16 + bt * 8 + 2 * t4;
                Gs0[r0 * 68 + col]           = acc0[bt][0];
                Gs0[r0 * 68 + col + 1]       = acc0[bt][1];
                Gs0[(r0 + 8) * 68 + col]     = acc0[bt][2];
                Gs0[(r0 + 8) * 68 + col + 1] = acc0[bt][3];
                Gs1[r0 * 68 + col]           = acc1[bt][0];
                Gs1[r0 * 68 + col + 1]       = acc1[bt][1];
                Gs1[(r0 + 8) * 68 + col]     = acc1[bt][2];
                Gs1[(r0 + 8) * 68 + col + 1] = acc1[bt][3];
            }
        }
        __syncthreads();

        // cell epilogues: layer1[t] and layer0[t+1]
#pragma unroll
        for (int it = 0; it < 2; it++) {
            int cell = tid + it * 256;
            int v = cell & 7, b = cell >> 3;
            int u = c * 8 + v;
            int fidx = ((c * 256 + ((b >> 3) * 4 + (v & 3)) * 8 + (b & 7)) << 1) + (v >> 2);

            // layer 1 step t
            {
                float gi = Gs1[v * 68 + b]        + sB[v];
                float gf = Gs1[(8 + v) * 68 + b]  + sB[8 + v];
                float go = Gs1[(16 + v) * 68 + b] + sB[16 + v];
                float gg = Gs1[(24 + v) * 68 + b] + sB[24 + v];
                float cn = sigmoidf_(gf) * c1r[it] + sigmoidf_(gi) * tanhf(gg);
                float hn = sigmoidf_(go) * tanhf(cn);
                c1r[it] = cn;
                out[((size_t)b * S_ + t) * H_ + u] = hn;
                wH1[fidx] = f2tf_f(hn);
                if (t == S_ - 1) {
                    out[(size_t)OUT_ELEMS + 1ull * BH_ + (size_t)b * H_ + u] = hn;
                    out[(size_t)OUT_ELEMS + 3ull * BH_ + (size_t)b * H_ + u] = cn;
                }
            }
            // layer 0 step t+1
            if (t < S_ - 1) {
                size_t gbase = ((size_t)(t + 1) * B_ + b) * G_ + c * 32;
                float gi = Gs0[v * 68 + b]        + g_G0[gbase + v];
                float gf = Gs0[(8 + v) * 68 + b]  + g_G0[gbase + 8 + v];
                float go = Gs0[(16 + v) * 68 + b] + g_G0[gbase + 16 + v];
                float gg = Gs0[(24 + v) * 68 + b] + g_G0[gbase + 24 + v];
                float cn = sigmoidf_(gf) * c0r[it] + sigmoidf_(gi) * tanhf(gg);
                float hn = sigmoidf_(go) * tanhf(cn);
                c0r[it] = cn;
                wH0[fidx] = f2tf_f(hn);
                if (t == S_ - 2) {
                    out[(size_t)OUT_ELEMS + (size_t)b * H_ + u]              = hn;
                    out[(size_t)OUT_ELEMS + 2ull * BH_ + (size_t)b * H_ + u] = cn;
                }
            }
        }
        if (t + 1 < S_) gsync();
    }
}

// ---------------- launch ----------------
extern "C" void kernel_launch(void* const* d_in, const int* in_sizes, int n_in,
                              void* d_out, int out_size)
{
    const float* x   = (const float*)d_in[0];
    const float* Wx0 = (const float*)d_in[1];
    const float* Wh0 = (const float*)d_in[2];
    const float* bx0 = (const float*)d_in[3];
    const float* bh0 = (const float*)d_in[4];
    const float* Wx1 = (const float*)d_in[5];
    const float* Wh1 = (const float*)d_in[6];
    const float* bx1 = (const float*)d_in[7];
    const float* bh1 = (const float*)d_in[8];
    float* out = (float*)d_out;

    static bool attr_done = false;
    if (!attr_done) {
        cudaFuncSetAttribute(lstm_persist,
                             cudaFuncAttributeMaxDynamicSharedMemorySize, SM_TOT);
        attr_done = true;
    }

    convert_nat<<<2048, 256>>>(Wx0, bx0, bh0, bx1, bh1);
    convert_frag<<<4096, 256>>>(Wh0, Wx1, Wh1);
    init_kernel<<<1, 32>>>();
    precompute_kernel<<<dim3(G_ / 128, (S_ * B_) / 128), 256>>>(x);
    lstm_persist<<<NCTA, NTHR, SM_TOT>>>(out);
}

// round 4
// speedup vs baseline: 1.2383x; 1.0177x over previous
#include <cuda_runtime.h>
#include <cstdint>

// Problem dims
#define B_  64
#define S_  512
#define I_  512
#define H_  1024
#define G_  4096          // 4*H
#define BH_ (B_*H_)       // 65536
#define OUT_ELEMS (B_*S_*H_)   // 33554432

#define NCTA 128
#define NTHR 512
#define NCH  16           // K-chunks of 64 per 1024-wide matrix

// persistent-kernel smem plan
#define ST_SZ  40960      // per stage: 16KB A (2 matrices) + 24KB B (padded)
#define NST    5
#define SM_GS0 204800
#define SM_GS1 213504
#define SM_BI  222208
#define SM_TOT 222336

// ---------------- device scratch (static, allowed) ----------------
__device__ float  g_Wx0p[G_*I_];            // tf32-rounded, gate-permuted rows (for precompute)
__device__ float  g_b0p[G_];                // bx0+bh0, permuted (folded into G0)
__device__ float  g_b1p[G_];                // bx1+bh1, permuted
__device__ float4 g_A0[(size_t)NCTA*NCH*512];  // Wh0 fragment-major
__device__ float4 g_A1[(size_t)NCTA*NCH*512];  // Wx1
__device__ float4 g_A2[(size_t)NCTA*NCH*512];  // Wh1
__device__ float  g_G0[(size_t)S_*B_*G_];   // x-path preactivations [t][b][prow] (512MB)
__device__ float4 g_h0F[2][16384];          // h0 fragment-major, double buffered
__device__ float4 g_h1F[2][16384];          // h1 fragment-major
__device__ unsigned g_barCount;
__device__ volatile unsigned g_barGen;

// ---------------- helpers ----------------
__device__ __forceinline__ float f2tf_f(float f) {
    uint32_t r;
    asm("cvt.rna.tf32.f32 %0, %1;" : "=r"(r) : "f"(f));
    return __uint_as_float(r);
}

__device__ __forceinline__ void mma_tf32(float* d, float4 a, float2 b) {
    asm volatile(
        "mma.sync.aligned.m16n8k8.row.col.f32.tf32.tf32.f32 "
        "{%0,%1,%2,%3}, {%4,%5,%6,%7}, {%8,%9}, {%0,%1,%2,%3};\n"
        : "+f"(d[0]), "+f"(d[1]), "+f"(d[2]), "+f"(d[3])
        : "r"(__float_as_uint(a.x)), "r"(__float_as_uint(a.y)),
          "r"(__float_as_uint(a.z)), "r"(__float_as_uint(a.w)),
          "r"(__float_as_uint(b.x)), "r"(__float_as_uint(b.y)));
}

__device__ __forceinline__ float sigmoidf_(float x) { return 1.0f / (1.0f + expf(-x)); }

__device__ __forceinline__ void cpa16(uint32_t dst, const void* src) {
    asm volatile("cp.async.cg.shared.global [%0], [%1], 16;\n" :: "r"(dst), "l"(src));
}
__device__ __forceinline__ void cp_commit() { asm volatile("cp.async.commit_group;\n"); }
template<int N> __device__ __forceinline__ void cp_waitN() {
    asm volatile("cp.async.wait_group %0;\n" :: "n"(N));
}

// grid barrier (all NCTA CTAs co-resident)
__device__ __forceinline__ void gsync() {
    __syncthreads();
    if (threadIdx.x == 0) {
        unsigned gen = g_barGen;
        __threadfence();
        if (atomicAdd(&g_barCount, 1u) == NCTA - 1) {
            g_barCount = 0;
            __threadfence();
            g_barGen = gen + 1;
        } else {
            while (g_barGen == gen) { }
            __threadfence();
        }
    }
    __syncthreads();
}

// Row permutation: prow = (u/8)*32 + q*8 + (u%8); CTA c owns units [8c,8c+8).

// ---------------- convert: natural Wx0 + biases ----------------
__global__ void __launch_bounds__(256) convert_nat(
    const float* __restrict__ Wx0, const float* __restrict__ bx0, const float* __restrict__ bh0,
    const float* __restrict__ bx1, const float* __restrict__ bh1)
{
    const int total = G_ * I_;
    for (int i = blockIdx.x * blockDim.x + threadIdx.x; i < total;
         i += gridDim.x * blockDim.x) {
        int prow = i / I_;
        int k    = i - prow * I_;
        int u    = ((prow >> 5) << 3) + (prow & 7);
        int q    = (prow >> 3) & 3;
        int orig = q * H_ + u;
        g_Wx0p[i] = f2tf_f(Wx0[(size_t)orig * I_ + k]);
        if (k == 0) {
            g_b0p[prow] = bx0[orig] + bh0[orig];
            g_b1p[prow] = bx1[orig] + bh1[orig];
        }
    }
}

// ---------------- convert: fragment-major recurrent weights ----------------
__global__ void __launch_bounds__(256) convert_frag(
    const float* __restrict__ Wh0, const float* __restrict__ Wx1, const float* __restrict__ Wh1)
{
    const int total = NCTA * NCH * 512;
    for (int idx = blockIdx.x * blockDim.x + threadIdx.x; idx < total;
         idx += gridDim.x * blockDim.x) {
        int lane = idx & 31;
        int kk   = (idx >> 5) & 7;
        int wm   = (idx >> 8) & 1;
        int ch   = (idx >> 9) & 15;
        int c    = idx >> 13;
        int g4 = lane >> 2, t4 = lane & 3;
        int p0 = wm * 16 + g4;
        int q0 = p0 >> 3, v = p0 & 7;
        int o0 = q0 * H_ + c * 8 + v;
        int k  = ch * 64 + kk * 8 + t4;
        size_t r0 = (size_t)o0 * H_ + k;
        size_t r1 = r0 + (size_t)H_ * H_;
        g_A0[idx] = make_float4(f2tf_f(Wh0[r0]), f2tf_f(Wh0[r1]),
                                f2tf_f(Wh0[r0 + 4]), f2tf_f(Wh0[r1 + 4]));
        g_A1[idx] = make_float4(f2tf_f(Wx1[r0]), f2tf_f(Wx1[r1]),
                                f2tf_f(Wx1[r0 + 4]), f2tf_f(Wx1[r1 + 4]));
        g_A2[idx] = make_float4(f2tf_f(Wh1[r0]), f2tf_f(Wh1[r1]),
                                f2tf_f(Wh1[r0 + 4]), f2tf_f(Wh1[r1 + 4]));
    }
}

// ---------------- init (every replay): barrier state only ----------------
__global__ void init_kernel() {
    if (threadIdx.x == 0) { g_barCount = 0; g_barGen = 0; }
}

// ---------------- x-path precompute: G0 = x@Wx0p^T + b0p ----------------
__global__ void __launch_bounds__(256, 1) precompute_kernel(const float* __restrict__ x)
{
    __shared__ float As[128][20];
    __shared__ float Bs[128][20];

    const int tid  = threadIdx.x;
    const int w    = tid >> 5;
    const int lane = tid & 31;
    const int wM   = w >> 2;
    const int wN   = w & 3;
    const int mBase = blockIdx.y * 128;
    const int nBase = blockIdx.x * 128;
    const int g4 = lane >> 2;
    const int t4 = lane & 3;

    float acc[4][4][4];
#pragma unroll
    for (int mt = 0; mt < 4; mt++)
#pragma unroll
        for (int nt = 0; nt < 4; nt++)
#pragma unroll
            for (int e = 0; e < 4; e++) acc[mt][nt][e] = 0.0f;

    for (int kc = 0; kc < I_; kc += 16) {
#pragma unroll
        for (int it = 0; it < 2; it++) {
            int i  = tid + it * 256;
            int r  = i >> 2;
            int c4 = (i & 3) * 4;
            int m  = mBase + r;
            int tt = m >> 6;
            int bb = m & 63;
            float4 v = *(const float4*)(x + ((size_t)bb * S_ + tt) * I_ + kc + c4);
            As[r][c4 + 0] = f2tf_f(v.x); As[r][c4 + 1] = f2tf_f(v.y);
            As[r][c4 + 2] = f2tf_f(v.z); As[r][c4 + 3] = f2tf_f(v.w);
        }
#pragma unroll
        for (int it = 0; it < 2; it++) {
            int i  = tid + it * 256;
            int r  = i >> 2;
            int c4 = (i & 3) * 4;
            float4 v = *(const float4*)(g_Wx0p + (size_t)(nBase + r) * I_ + kc + c4);
            Bs[r][c4 + 0] = v.x; Bs[r][c4 + 1] = v.y;
            Bs[r][c4 + 2] = v.z; Bs[r][c4 + 3] = v.w;
        }
        __syncthreads();

#pragma unroll
        for (int kk = 0; kk < 2; kk++) {
            int k = kk * 8;
            float2 bf[4];
#pragma unroll
            for (int nt = 0; nt < 4; nt++) {
                int n = wN * 32 + nt * 8 + g4;
                bf[nt] = make_float2(Bs[n][k + t4], Bs[n][k + t4 + 4]);
            }
#pragma unroll
            for (int mt = 0; mt < 4; mt++) {
                int r = wM * 64 + mt * 16 + g4;
                float4 af = make_float4(As[r][k + t4], As[r + 8][k + t4],
                                        As[r][k + t4 + 4], As[r + 8][k + t4 + 4]);
#pragma unroll
                for (int nt = 0; nt < 4; nt++)
                    mma_tf32(acc[mt][nt], af, bf[nt]);
            }
        }
        __syncthreads();
    }

#pragma unroll
    for (int mt = 0; mt < 4; mt++) {
        int r0 = mBase + wM * 64 + mt * 16 + g4;
        int r1 = r0 + 8;
#pragma unroll
        for (int nt = 0; nt < 4; nt++) {
            int n0 = nBase + wN * 32 + nt * 8 + t4 * 2;
            float2 bv = *(const float2*)(g_b0p + n0);
            *(float2*)(g_G0 + (size_t)r0 * G_ + n0) =
                make_float2(acc[mt][nt][0] + bv.x, acc[mt][nt][1] + bv.y);
            *(float2*)(g_G0 + (size_t)r1 * G_ + n0) =
                make_float2(acc[mt][nt][2] + bv.x, acc[mt][nt][3] + bv.y);
        }
    }
}

// ---------------- persistent recurrent kernel ----------------
// 512 threads: warp w: ks = w>>3 (K-split half), wm = (w>>2)&1, wb = w&3.
// Fused interval: layer0[t+1] (Wh0 x h0[t]) + layer1[t] (Wx1 x h0[t] + Wh1 x h1[t-1]).
// 32 chunks of K=64: ch<16 stage {Wh0,Wx1} + h0; ch>=16 stage {Wh1} + h1.
// 5-stage cp.async pipeline, prefetch distance 4.

struct StageSrc { const float4* a0; const float4* a1; const float4* b; };

__device__ __forceinline__ void stage_chunk(char* sm, int stg, StageSrc s, int tid)
{
    char* sa = sm + stg * ST_SZ;
    uint32_t aB = (uint32_t)__cvta_generic_to_shared(sa);
    uint32_t bB = aB + 16384;
    cpa16(aB + (uint32_t)tid * 16, s.a0 + tid);
    if (s.a1) cpa16(aB + 8192 + (uint32_t)tid * 16, s.a1 + tid);
#pragma unroll
    for (int it = 0; it < 2; it++) {
        int s4 = tid + it * 512;
        cpa16(bB + (uint32_t)((s4 >> 2) * 96 + (s4 & 3) * 16), s.b + s4);
    }
    cp_commit();
}

__global__ void __launch_bounds__(NTHR, 1) lstm_persist(float* __restrict__ out)
{
    extern __shared__ char sm[];
    float* Gs0 = (float*)(sm + SM_GS0);
    float* Gs1 = (float*)(sm + SM_GS1);
    float* sB  = (float*)(sm + SM_BI);

    const int c    = blockIdx.x;
    const int tid  = threadIdx.x;
    const int w    = tid >> 5;
    const int lane = tid & 31;
    const int ks   = w >> 3;     // 0..1 : K-split half (kk = ks*4 + kq)
    const int wm   = (w >> 2) & 1;   // prow half
    const int wb   = w & 3;      // batch group of 16
    const int g4   = lane >> 2;
    const int t4   = lane & 3;
    const int v    = tid & 7;    // unit within CTA
    const int b    = tid >> 3;   // batch (0..63)
    const int u    = c * 8 + v;
    const int fidx = ((c * 256 + ((b >> 3) * 4 + (v & 3)) * 8 + (b & 7)) << 1) + (v >> 2);

    if (tid < 32) sB[tid] = g_b1p[c * 32 + tid];
    __syncthreads();

    float c0r = 0.f, c1r = 0.f;

    // preamble: h0[0] from G0[0] (h=0), zero h1[-1] fragments
    {
        float* h0w0 = (float*)g_h0F[0];
        float* h1w0 = (float*)g_h1F[0];
        size_t gbase = (size_t)b * G_ + c * 32;
        float gi = g_G0[gbase + v];
        float go = g_G0[gbase + 16 + v];
        float gg = g_G0[gbase + 24 + v];
        float cn = sigmoidf_(gi) * tanhf(gg);
        float hn = sigmoidf_(go) * tanhf(cn);
        c0r = cn;
        h0w0[fidx] = f2tf_f(hn);
        h1w0[fidx] = 0.f;
    }
    gsync();

    const float4* a0B = g_A0 + (size_t)c * (NCH * 512);
    const float4* a1B = g_A1 + (size_t)c * (NCH * 512);
    const float4* a2B = g_A2 + (size_t)c * (NCH * 512);

    for (int t = 0; t < S_; t++) {
        // prefetch next layer0's G0 operands (hide DRAM latency behind mma loop)
        float p_gi = 0.f, p_gf = 0.f, p_go = 0.f, p_gg = 0.f;
        if (t + 1 < S_) {
            size_t gb = ((size_t)(t + 1) * B_ + b) * G_ + c * 32;
            p_gi = g_G0[gb + v];
            p_gf = g_G0[gb + 8 + v];
            p_go = g_G0[gb + 16 + v];
            p_gg = g_G0[gb + 24 + v];
        }

        const float4* bH0 = g_h0F[t & 1];          // h0[t]
        float*        wH0 = (float*)g_h0F[(t + 1) & 1];
        const float4* bH1 = g_h1F[t & 1];          // h1[t-1]
        float*        wH1 = (float*)g_h1F[(t + 1) & 1];

        auto src_of = [&](int ch) -> StageSrc {
            StageSrc s;
            if (ch < 16) {
                s.a0 = a0B + (size_t)ch * 512;
                s.a1 = a1B + (size_t)ch * 512;
                s.b  = bH0 + (size_t)ch * 1024;
            } else {
                s.a0 = a2B + (size_t)(ch - 16) * 512;
                s.a1 = nullptr;
                s.b  = bH1 + (size_t)(ch - 16) * 1024;
            }
            return s;
        };

        float acc0[2][4], acc1[2][4];
#pragma unroll
        for (int bt = 0; bt < 2; bt++)
#pragma unroll
            for (int e = 0; e < 4; e++) { acc0[bt][e] = 0.f; acc1[bt][e] = 0.f; }

        // prologue: fill 4 stages
        stage_chunk(sm, 0, src_of(0), tid);
        stage_chunk(sm, 1, src_of(1), tid);
        stage_chunk(sm, 2, src_of(2), tid);
        stage_chunk(sm, 3, src_of(3), tid);

        for (int ch = 0; ch < 32; ch++) {
            if      (ch < 29)  cp_waitN<3>();
            else if (ch == 29) cp_waitN<2>();
            else if (ch == 30) cp_waitN<1>();
            else               cp_waitN<0>();
            __syncthreads();
            if (ch + 4 < 32) stage_chunk(sm, (ch + 4) % NST, src_of(ch + 4), tid);

            int stg = ch % NST;
            const float4* Af = (const float4*)(sm + stg * ST_SZ);
            const char*   Bb = sm + stg * ST_SZ + 16384;
            if (ch < 16) {
#pragma unroll
                for (int kq = 0; kq < 4; kq++) {
                    int kk = ks * 4 + kq;
                    const char* bp = Bb + ((kk * 8 + wb * 2) * 4 + t4) * 96 + g4 * 8;
                    float2 b0f = *(const float2*)bp;
                    float2 b1f = *(const float2*)(bp + 384);
                    float4 a0 = Af[(wm * 8 + kk) * 32 + lane];
                    float4 a1 = Af[512 + (wm * 8 + kk) * 32 + lane];
                    mma_tf32(acc0[0], a0, b0f);
                    mma_tf32(acc0[1], a0, b1f);
                    mma_tf32(acc1[0], a1, b0f);
                    mma_tf32(acc1[1], a1, b1f);
                }
            } else {
#pragma unroll
                for (int kq = 0; kq < 4; kq++) {
                    int kk = ks * 4 + kq;
                    const char* bp = Bb + ((kk * 8 + wb * 2) * 4 + t4) * 96 + g4 * 8;
                    float2 b0f = *(const float2*)bp;
                    float2 b1f = *(const float2*)(bp + 384);
                    float4 a0 = Af[(wm * 8 + kk) * 32 + lane];
                    mma_tf32(acc1[0], a0, b0f);
                    mma_tf32(acc1[1], a0, b1f);
                }
            }
        }

        // ---- reduce the two K-split halves, then cell epilogue ----
        int r0 = wm * 16 + g4;
        if (ks == 1) {
#pragma unroll
            for (int bt = 0; bt < 2; bt++) {
                int col = wb * 16 + bt * 8 + 2 * t4;
                Gs0[r0 * 68 + col]           = acc0[bt][0];
                Gs0[r0 * 68 + col + 1]       = acc0[bt][1];
                Gs0[(r0 + 8) * 68 + col]     = acc0[bt][2];
                Gs0[(r0 + 8) * 68 + col + 1] = acc0[bt][3];
                Gs1[r0 * 68 + col]           = acc1[bt][0];
                Gs1[r0 * 68 + col + 1]       = acc1[bt][1];
                Gs1[(r0 + 8) * 68 + col]     = acc1[bt][2];
                Gs1[(r0 + 8) * 68 + col + 1] = acc1[bt][3];
            }
        }
        __syncthreads();
        if (ks == 0) {
#pragma unroll
            for (int bt = 0; bt < 2; bt++) {
                int col = wb * 16 + bt * 8 + 2 * t4;
                Gs0[r0 * 68 + col]           += acc0[bt][0];
                Gs0[r0 * 68 + col + 1]       += acc0[bt][1];
                Gs0[(r0 + 8) * 68 + col]     += acc0[bt][2];
                Gs0[(r0 + 8) * 68 + col + 1] += acc0[bt][3];
                Gs1[r0 * 68 + col]           += acc1[bt][0];
                Gs1[r0 * 68 + col + 1]       += acc1[bt][1];
                Gs1[(r0 + 8) * 68 + col]     += acc1[bt][2];
                Gs1[(r0 + 8) * 68 + col + 1] += acc1[bt][3];
            }
        }
        __syncthreads();

        // layer 1 step t
        {
            float gi = Gs1[v * 68 + b]        + sB[v];
            float gf = Gs1[(8 + v) * 68 + b]  + sB[8 + v];
            float go = Gs1[(16 + v) * 68 + b] + sB[16 + v];
            float gg = Gs1[(24 + v) * 68 + b] + sB[24 + v];
            float cn = sigmoidf_(gf) * c1r + sigmoidf_(gi) * tanhf(gg);
            float hn = sigmoidf_(go) * tanhf(cn);
            c1r = cn;
            out[((size_t)b * S_ + t) * H_ + u] = hn;
            wH1[fidx] = f2tf_f(hn);
            if (t == S_ - 1) {
                out[(size_t)OUT_ELEMS + 1ull * BH_ + (size_t)b * H_ + u] = hn;
                out[(size_t)OUT_ELEMS + 3ull * BH_ + (size_t)b * H_ + u] = cn;
            }
        }
        // layer 0 step t+1
        if (t < S_ - 1) {
            float gi = Gs0[v * 68 + b]        + p_gi;
            float gf = Gs0[(8 + v) * 68 + b]  + p_gf;
            float go = Gs0[(16 + v) * 68 + b] + p_go;
            float gg = Gs0[(24 + v) * 68 + b] + p_gg;
            float cn = sigmoidf_(gf) * c0r + sigmoidf_(gi) * tanhf(gg);
            float hn = sigmoidf_(go) * tanhf(cn);
            c0r = cn;
            wH0[fidx] = f2tf_f(hn);
            if (t == S_ - 2) {
                out[(size_t)OUT_ELEMS + (size_t)b * H_ + u]              = hn;
                out[(size_t)OUT_ELEMS + 2ull * BH_ + (size_t)b * H_ + u] = cn;
            }
        }
        if (t + 1 < S_) gsync();
    }
}

// ---------------- launch ----------------
extern "C" void kernel_launch(void* const* d_in, const int* in_sizes, int n_in,
                              void* d_out, int out_size)
{
    const float* x   = (const float*)d_in[0];
    const float* Wx0 = (const float*)d_in[1];
    const float* Wh0 = (const float*)d_in[2];
    const float* bx0 = (const float*)d_in[3];
    const float* bh0 = (const float*)d_in[4];
    const float* Wx1 = (const float*)d_in[5];
    const float* Wh1 = (const float*)d_in[6];
    const float* bx1 = (const float*)d_in[7];
    const float* bh1 = (const float*)d_in[8];
    float* out = (float*)d_out;

    static bool attr_done = false;
    if (!attr_done) {
        cudaFuncSetAttribute(lstm_persist,
                             cudaFuncAttributeMaxDynamicSharedMemorySize, SM_TOT);
        attr_done = true;
    }

    convert_nat<<<2048, 256>>>(Wx0, bx0, bh0, bx1, bh1);
    convert_frag<<<4096, 256>>>(Wh0, Wx1, Wh1);
    init_kernel<<<1, 32>>>();
    precompute_kernel<<<dim3(G_ / 128, (S_ * B_) / 128), 256>>>(x);
    lstm_persist<<<NCTA, NTHR, SM_TOT>>>(out);
}

// round 5
// speedup vs baseline: 1.2827x; 1.0358x over previous
#include <cuda_runtime.h>
#include <cstdint>

// Problem dims
#define B_  64
#define S_  512
#define I_  512
#define H_  1024
#define G_  4096          // 4*H
#define BH_ (B_*H_)       // 65536
#define OUT_ELEMS (B_*S_*H_)   // 33554432

#define NCTA 128
#define NTHR 512
#define NCH  16           // K-chunks of 64 per 1024-wide matrix

// persistent-kernel smem plan (TMA-staged, dense layouts)
// stage: [0,16384) B (h fragments), [16384,24576) A0, [24576,32768) A1
#define ST_SZ  32768
#define NST    4
#define SM_GS0 (NST*ST_SZ)          // 131072
#define SM_GS1 (SM_GS0 + 8704)      // 139776
#define SM_BI  (SM_GS1 + 8704)      // 148480
#define SM_MB  (SM_BI + 128)        // 148608
#define SM_TOT (SM_MB + 64)         // 148672

// ---------------- device scratch (static, allowed) ----------------
__device__ float  g_Wx0p[G_*I_];            // tf32-rounded, gate-permuted rows (for precompute)
__device__ float  g_b0p[G_];                // bx0+bh0, permuted (folded into G0)
__device__ float  g_b1p[G_];                // bx1+bh1, permuted
__device__ float4 g_A0[(size_t)NCTA*NCH*512];  // Wh0 fragment-major
__device__ float4 g_A1[(size_t)NCTA*NCH*512];  // Wx1
__device__ float4 g_A2[(size_t)NCTA*NCH*512];  // Wh1
__device__ float  g_G0[(size_t)S_*B_*G_];   // x-path preactivations [t][b][prow] (512MB)
__device__ float4 g_h0F[2][16384];          // h0 fragment-major, double buffered
__device__ float4 g_h1F[2][16384];          // h1 fragment-major
__device__ unsigned g_barCount;
__device__ volatile unsigned g_barGen;

// ---------------- helpers ----------------
__device__ __forceinline__ float f2tf_f(float f) {
    uint32_t r;
    asm("cvt.rna.tf32.f32 %0, %1;" : "=r"(r) : "f"(f));
    return __uint_as_float(r);
}

__device__ __forceinline__ void mma_tf32(float* d, float4 a, float2 b) {
    asm volatile(
        "mma.sync.aligned.m16n8k8.row.col.f32.tf32.tf32.f32 "
        "{%0,%1,%2,%3}, {%4,%5,%6,%7}, {%8,%9}, {%0,%1,%2,%3};\n"
        : "+f"(d[0]), "+f"(d[1]), "+f"(d[2]), "+f"(d[3])
        : "r"(__float_as_uint(a.x)), "r"(__float_as_uint(a.y)),
          "r"(__float_as_uint(a.z)), "r"(__float_as_uint(a.w)),
          "r"(__float_as_uint(b.x)), "r"(__float_as_uint(b.y)));
}

__device__ __forceinline__ float sigmoidf_(float x) { return 1.0f / (1.0f + expf(-x)); }

// ---- TMA bulk + mbarrier machinery ----
__device__ __forceinline__ void mbar_init(uint32_t addr, uint32_t count) {
    asm volatile("mbarrier.init.shared.b64 [%0], %1;" :: "r"(addr), "r"(count) : "memory");
}
__device__ __forceinline__ void mbar_expect_tx(uint32_t addr, uint32_t bytes) {
    asm volatile("mbarrier.arrive.expect_tx.shared.b64 _, [%0], %1;"
                 :: "r"(addr), "r"(bytes) : "memory");
}
__device__ __forceinline__ void bulk_g2s(uint32_t dst, const void* src,
                                         uint32_t bytes, uint32_t mbar) {
    asm volatile(
        "cp.async.bulk.shared::cta.global.mbarrier::complete_tx::bytes [%0], [%1], %2, [%3];"
        :: "r"(dst), "l"(src), "r"(bytes), "r"(mbar) : "memory");
}
__device__ __forceinline__ void mbar_wait(uint32_t mbar, uint32_t parity) {
    asm volatile(
        "{\n\t"
        ".reg .pred P;\n\t"
        "WAIT_LOOP_%=:\n\t"
        "mbarrier.try_wait.parity.acquire.cta.shared::cta.b64 P, [%0], %1, 0x989680;\n\t"
        "@P bra.uni WAIT_DONE_%=;\n\t"
        "bra.uni WAIT_LOOP_%=;\n\t"
        "WAIT_DONE_%=:\n\t"
        "}"
        :: "r"(mbar), "r"(parity) : "memory");
}

// grid barrier (all NCTA CTAs co-resident)
__device__ __forceinline__ void gsync() {
    __syncthreads();
    if (threadIdx.x == 0) {
        unsigned gen = g_barGen;
        __threadfence();
        if (atomicAdd(&g_barCount, 1u) == NCTA - 1) {
            g_barCount = 0;
            __threadfence();
            g_barGen = gen + 1;
        } else {
            while (g_barGen == gen) { }
            __threadfence();
        }
    }
    __syncthreads();
}

// Row permutation: prow = (u/8)*32 + q*8 + (u%8); CTA c owns units [8c,8c+8).

// ---------------- convert: natural Wx0 + biases ----------------
__global__ void __launch_bounds__(256) convert_nat(
    const float* __restrict__ Wx0, const float* __restrict__ bx0, const float* __restrict__ bh0,
    const float* __restrict__ bx1, const float* __restrict__ bh1)
{
    const int total = G_ * I_;
    for (int i = blockIdx.x * blockDim.x + threadIdx.x; i < total;
         i += gridDim.x * blockDim.x) {
        int prow = i / I_;
        int k    = i - prow * I_;
        int u    = ((prow >> 5) << 3) + (prow & 7);
        int q    = (prow >> 3) & 3;
        int orig = q * H_ + u;
        g_Wx0p[i] = f2tf_f(Wx0[(size_t)orig * I_ + k]);
        if (k == 0) {
            g_b0p[prow] = bx0[orig] + bh0[orig];
            g_b1p[prow] = bx1[orig] + bh1[orig];
        }
    }
}

// ---------------- convert: fragment-major recurrent weights ----------------
__global__ void __launch_bounds__(256) convert_frag(
    const float* __restrict__ Wh0, const float* __restrict__ Wx1, const float* __restrict__ Wh1)
{
    const int total = NCTA * NCH * 512;
    for (int idx = blockIdx.x * blockDim.x + threadIdx.x; idx < total;
         idx += gridDim.x * blockDim.x) {
        int lane = idx & 31;
        int kk   = (idx >> 5) & 7;
        int wm   = (idx >> 8) & 1;
        int ch   = (idx >> 9) & 15;
        int c    = idx >> 13;
        int g4 = lane >> 2, t4 = lane & 3;
        int p0 = wm * 16 + g4;
        int q0 = p0 >> 3, v = p0 & 7;
        int o0 = q0 * H_ + c * 8 + v;
        int k  = ch * 64 + kk * 8 + t4;
        size_t r0 = (size_t)o0 * H_ + k;
        size_t r1 = r0 + (size_t)H_ * H_;
        g_A0[idx] = make_float4(f2tf_f(Wh0[r0]), f2tf_f(Wh0[r1]),
                                f2tf_f(Wh0[r0 + 4]), f2tf_f(Wh0[r1 + 4]));
        g_A1[idx] = make_float4(f2tf_f(Wx1[r0]), f2tf_f(Wx1[r1]),
                                f2tf_f(Wx1[r0 + 4]), f2tf_f(Wx1[r1 + 4]));
        g_A2[idx] = make_float4(f2tf_f(Wh1[r0]), f2tf_f(Wh1[r1]),
                                f2tf_f(Wh1[r0 + 4]), f2tf_f(Wh1[r1 + 4]));
    }
}

// ---------------- init (every replay): barrier state only ----------------
__global__ void init_kernel() {
    if (threadIdx.x == 0) { g_barCount = 0; g_barGen = 0; }
}

// ---------------- x-path precompute: G0 = x@Wx0p^T + b0p ----------------
__global__ void __launch_bounds__(256, 1) precompute_kernel(const float* __restrict__ x)
{
    __shared__ float As[128][20];
    __shared__ float Bs[128][20];

    const int tid  = threadIdx.x;
    const int w    = tid >> 5;
    const int lane = tid & 31;
    const int wM   = w >> 2;
    const int wN   = w & 3;
    const int mBase = blockIdx.y * 128;
    const int nBase = blockIdx.x * 128;
    const int g4 = lane >> 2;
    const int t4 = lane & 3;

    float acc[4][4][4];
#pragma unroll
    for (int mt = 0; mt < 4; mt++)
#pragma unroll
        for (int nt = 0; nt < 4; nt++)
#pragma unroll
            for (int e = 0; e < 4; e++) acc[mt][nt][e] = 0.0f;

    for (int kc = 0; kc < I_; kc += 16) {
#pragma unroll
        for (int it = 0; it < 2; it++) {
            int i  = tid + it * 256;
            int r  = i >> 2;
            int c4 = (i & 3) * 4;
            int m  = mBase + r;
            int tt = m >> 6;
            int bb = m & 63;
            float4 v = *(const float4*)(x + ((size_t)bb * S_ + tt) * I_ + kc + c4);
            As[r][c4 + 0] = f2tf_f(v.x); As[r][c4 + 1] = f2tf_f(v.y);
            As[r][c4 + 2] = f2tf_f(v.z); As[r][c4 + 3] = f2tf_f(v.w);
        }
#pragma unroll
        for (int it = 0; it < 2; it++) {
            int i  = tid + it * 256;
            int r  = i >> 2;
            int c4 = (i & 3) * 4;
            float4 v = *(const float4*)(g_Wx0p + (size_t)(nBase + r) * I_ + kc + c4);
            Bs[r][c4 + 0] = v.x; Bs[r][c4 + 1] = v.y;
            Bs[r][c4 + 2] = v.z; Bs[r][c4 + 3] = v.w;
        }
        __syncthreads();

#pragma unroll
        for (int kk = 0; kk < 2; kk++) {
            int k = kk * 8;
            float2 bf[4];
#pragma unroll
            for (int nt = 0; nt < 4; nt++) {
                int n = wN * 32 + nt * 8 + g4;
                bf[nt] = make_float2(Bs[n][k + t4], Bs[n][k + t4 + 4]);
            }
#pragma unroll
            for (int mt = 0; mt < 4; mt++) {
                int r = wM * 64 + mt * 16 + g4;
                float4 af = make_float4(As[r][k + t4], As[r + 8][k + t4],
                                        As[r][k + t4 + 4], As[r + 8][k + t4 + 4]);
#pragma unroll
                for (int nt = 0; nt < 4; nt++)
                    mma_tf32(acc[mt][nt], af, bf[nt]);
            }
        }
        __syncthreads();
    }

#pragma unroll
    for (int mt = 0; mt < 4; mt++) {
        int r0 = mBase + wM * 64 + mt * 16 + g4;
        int r1 = r0 + 8;
#pragma unroll
        for (int nt = 0; nt < 4; nt++) {
            int n0 = nBase + wN * 32 + nt * 8 + t4 * 2;
            float2 bv = *(const float2*)(g_b0p + n0);
            *(float2*)(g_G0 + (size_t)r0 * G_ + n0) =
                make_float2(acc[mt][nt][0] + bv.x, acc[mt][nt][1] + bv.y);
            *(float2*)(g_G0 + (size_t)r1 * G_ + n0) =
                make_float2(acc[mt][nt][2] + bv.x, acc[mt][nt][3] + bv.y);
        }
    }
}

// ---------------- persistent recurrent kernel (TMA-staged) ----------------
// 512 threads: warp w: ks = w>>3 (K-split half), wm = (w>>2)&1, wb = w&3.
// Fused interval: layer0[t+1] (Wh0 x h0[t]) + layer1[t] (Wx1 x h0[t] + Wh1 x h1[t-1]).
// 32 chunks of K=64: ch<16 stage {Wh0,Wx1} + h0; ch>=16 stage {Wh1} + h1.
// 4-stage pipeline: stage = ch&3, parity = (ch>>2)&1 (8 uses/stage/step, even).

struct StageSrc { const float4* a0; const float4* a1; const float4* b; };

__global__ void __launch_bounds__(NTHR, 1) lstm_persist(float* __restrict__ out)
{
    extern __shared__ char sm[];
    float* Gs0 = (float*)(sm + SM_GS0);
    float* Gs1 = (float*)(sm + SM_GS1);
    float* sB  = (float*)(sm + SM_BI);
    const uint32_t smBase   = (uint32_t)__cvta_generic_to_shared(sm);
    const uint32_t mbarBase = smBase + SM_MB;

    const int c    = blockIdx.x;
    const int tid  = threadIdx.x;
    const int w    = tid >> 5;
    const int lane = tid & 31;
    const int ks   = w >> 3;         // K-split half (kk = ks*4 + kq)
    const int wm   = (w >> 2) & 1;   // prow half
    const int wb   = w & 3;          // batch group of 16
    const int g4   = lane >> 2;
    const int t4   = lane & 3;
    const int v    = tid & 7;        // unit within CTA
    const int b    = tid >> 3;       // batch (0..63)
    const int u    = c * 8 + v;
    const int fidx = ((c * 256 + ((b >> 3) * 4 + (v & 3)) * 8 + (b & 7)) << 1) + (v >> 2);

    if (tid == 0) {
#pragma unroll
        for (int s = 0; s < NST; s++) mbar_init(mbarBase + s * 8, 1);
    }
    if (tid < 32) sB[tid] = g_b1p[c * 32 + tid];
    asm volatile("fence.proxy.async.shared::cta;" ::: "memory");
    __syncthreads();

    float c0r = 0.f, c1r = 0.f;

    // preamble: h0[0] from G0[0] (h=0), zero h1[-1] fragments
    {
        float* h0w0 = (float*)g_h0F[0];
        float* h1w0 = (float*)g_h1F[0];
        size_t gbase = (size_t)b * G_ + c * 32;
        float gi = g_G0[gbase + v];
        float go = g_G0[gbase + 16 + v];
        float gg = g_G0[gbase + 24 + v];
        float cn = sigmoidf_(gi) * tanhf(gg);
        float hn = sigmoidf_(go) * tanhf(cn);
        c0r = cn;
        h0w0[fidx] = f2tf_f(hn);
        h1w0[fidx] = 0.f;
    }
    gsync();

    const float4* a0B = g_A0 + (size_t)c * (NCH * 512);
    const float4* a1B = g_A1 + (size_t)c * (NCH * 512);
    const float4* a2B = g_A2 + (size_t)c * (NCH * 512);

    for (int t = 0; t < S_; t++) {
        // prefetch next layer0's G0 operands (hide DRAM latency behind mma loop)
        float p_gi = 0.f, p_gf = 0.f, p_go = 0.f, p_gg = 0.f;
        if (t + 1 < S_) {
            size_t gb = ((size_t)(t + 1) * B_ + b) * G_ + c * 32;
            p_gi = g_G0[gb + v];
            p_gf = g_G0[gb + 8 + v];
            p_go = g_G0[gb + 16 + v];
            p_gg = g_G0[gb + 24 + v];
        }

        const float4* bH0 = g_h0F[t & 1];          // h0[t]
        float*        wH0 = (float*)g_h0F[(t + 1) & 1];
        const float4* bH1 = g_h1F[t & 1];          // h1[t-1]
        float*        wH1 = (float*)g_h1F[(t + 1) & 1];

        auto issue_chunk = [&](int ch) {
            StageSrc s;
            if (ch < 16) {
                s.a0 = a0B + (size_t)ch * 512;
                s.a1 = a1B + (size_t)ch * 512;
                s.b  = bH0 + (size_t)ch * 1024;
            } else {
                s.a0 = a2B + (size_t)(ch - 16) * 512;
                s.a1 = nullptr;
                s.b  = bH1 + (size_t)(ch - 16) * 1024;
            }
            uint32_t sb = smBase + (uint32_t)(ch & 3) * ST_SZ;
            uint32_t mb = mbarBase + (uint32_t)(ch & 3) * 8;
            uint32_t tx = (ch < 16) ? 32768u : 24576u;
            mbar_expect_tx(mb, tx);
            bulk_g2s(sb,          s.b,  16384, mb);
            bulk_g2s(sb + 16384,  s.a0, 8192,  mb);
            if (ch < 16) bulk_g2s(sb + 24576, s.a1, 8192, mb);
        };

        float acc0[2][4], acc1[2][4];
#pragma unroll
        for (int bt = 0; bt < 2; bt++)
#pragma unroll
            for (int e = 0; e < 4; e++) { acc0[bt][e] = 0.f; acc1[bt][e] = 0.f; }

        // prologue: fill all 4 stages
        if (tid == 0) {
            issue_chunk(0); issue_chunk(1); issue_chunk(2); issue_chunk(3);
        }

        for (int ch = 0; ch < 32; ch++) {
            mbar_wait(mbarBase + (uint32_t)(ch & 3) * 8, (uint32_t)((ch >> 2) & 1));

            const char*   stB = sm + (ch & 3) * ST_SZ;
            const float4* Af  = (const float4*)(stB + 16384);
            if (ch < 16) {
#pragma unroll
                for (int kq = 0; kq < 4; kq++) {
                    int kk = ks * 4 + kq;
                    const char* bp = stB + (((kk * 8 + wb * 2) * 4 + t4) * 64) + g4 * 8;
                    float2 b0f = *(const float2*)bp;
                    float2 b1f = *(const float2*)(bp + 256);
                    float4 a0 = Af[(wm * 8 + kk) * 32 + lane];
                    float4 a1 = Af[512 + (wm * 8 + kk) * 32 + lane];
                    mma_tf32(acc0[0], a0, b0f);
                    mma_tf32(acc0[1], a0, b1f);
                    mma_tf32(acc1[0], a1, b0f);
                    mma_tf32(acc1[1], a1, b1f);
                }
            } else {
#pragma unroll
                for (int kq = 0; kq < 4; kq++) {
                    int kk = ks * 4 + kq;
                    const char* bp = stB + (((kk * 8 + wb * 2) * 4 + t4) * 64) + g4 * 8;
                    float2 b0f = *(const float2*)bp;
                    float2 b1f = *(const float2*)(bp + 256);
                    float4 a0 = Af[(wm * 8 + kk) * 32 + lane];
                    mma_tf32(acc1[0], a0, b0f);
                    mma_tf32(acc1[1], a0, b1f);
                }
            }
            __syncthreads();               // everyone done with this stage
            if (tid == 0 && ch + 4 < 32) issue_chunk(ch + 4);
        }

        // ---- reduce the two K-split halves, then cell epilogue ----
        int r0 = wm * 16 + g4;
        if (ks == 1) {
#pragma unroll
            for (int bt = 0; bt < 2; bt++) {
                int col = wb * 16 + bt * 8 + 2 * t4;
                Gs0[r0 * 68 + col]           = acc0[bt][0];
                Gs0[r0 * 68 + col + 1]       = acc0[bt][1];
                Gs0[(r0 + 8) * 68 + col]     = acc0[bt][2];
                Gs0[(r0 + 8) * 68 + col + 1] = acc0[bt][3];
                Gs1[r0 * 68 + col]           = acc1[bt][0];
                Gs1[r0 * 68 + col + 1]       = acc1[bt][1];
                Gs1[(r0 + 8) * 68 + col]     = acc1[bt][2];
                Gs1[(r0 + 8) * 68 + col + 1] = acc1[bt][3];
            }
        }
        __syncthreads();
        if (ks == 0) {
#pragma unroll
            for (int bt = 0; bt < 2; bt++) {
                int col = wb * 16 + bt * 8 + 2 * t4;
                Gs0[r0 * 68 + col]           += acc0[bt][0];
                Gs0[r0 * 68 + col + 1]       += acc0[bt][1];
                Gs0[(r0 + 8) * 68 + col]     += acc0[bt][2];
                Gs0[(r0 + 8) * 68 + col + 1] += acc0[bt][3];
                Gs1[r0 * 68 + col]           += acc1[bt][0];
                Gs1[r0 * 68 + col + 1]       += acc1[bt][1];
                Gs1[(r0 + 8) * 68 + col]     += acc1[bt][2];
                Gs1[(r0 + 8) * 68 + col + 1] += acc1[bt][3];
            }
        }
        __syncthreads();

        // layer 1 step t
        {
            float gi = Gs1[v * 68 + b]        + sB[v];
            float gf = Gs1[(8 + v) * 68 + b]  + sB[8 + v];
            float go = Gs1[(16 + v) * 68 + b] + sB[16 + v];
            float gg = Gs1[(24 + v) * 68 + b] + sB[24 + v];
            float cn = sigmoidf_(gf) * c1r + sigmoidf_(gi) * tanhf(gg);
            float hn = sigmoidf_(go) * tanhf(cn);
            c1r = cn;
            out[((size_t)b * S_ + t) * H_ + u] = hn;
            wH1[fidx] = f2tf_f(hn);
            if (t == S_ - 1) {
                out[(size_t)OUT_ELEMS + 1ull * BH_ + (size_t)b * H_ + u] = hn;
                out[(size_t)OUT_ELEMS + 3ull * BH_ + (size_t)b * H_ + u] = cn;
            }
        }
        // layer 0 step t+1
        if (t < S_ - 1) {
            float gi = Gs0[v * 68 + b]        + p_gi;
            float gf = Gs0[(8 + v) * 68 + b]  + p_gf;
            float go = Gs0[(16 + v) * 68 + b] + p_go;
            float gg = Gs0[(24 + v) * 68 + b] + p_gg;
            float cn = sigmoidf_(gf) * c0r + sigmoidf_(gi) * tanhf(gg);
            float hn = sigmoidf_(go) * tanhf(cn);
            c0r = cn;
            wH0[fidx] = f2tf_f(hn);
            if (t == S_ - 2) {
                out[(size_t)OUT_ELEMS + (size_t)b * H_ + u]              = hn;
                out[(size_t)OUT_ELEMS + 2ull * BH_ + (size_t)b * H_ + u] = cn;
            }
        }
        if (t + 1 < S_) gsync();
    }
}

// ---------------- launch ----------------
extern "C" void kernel_launch(void* const* d_in, const int* in_sizes, int n_in,
                              void* d_out, int out_size)
{
    const float* x   = (const float*)d_in[0];
    const float* Wx0 = (const float*)d_in[1];
    const float* Wh0 = (const float*)d_in[2];
    const float* bx0 = (const float*)d_in[3];
    const float* bh0 = (const float*)d_in[4];
    const float* Wx1 = (const float*)d_in[5];
    const float* Wh1 = (const float*)d_in[6];
    const float* bx1 = (const float*)d_in[7];
    const float* bh1 = (const float*)d_in[8];
    float* out = (float*)d_out;

    static bool attr_done = false;
    if (!attr_done) {
        cudaFuncSetAttribute(lstm_persist,
                             cudaFuncAttributeMaxDynamicSharedMemorySize, SM_TOT);
        attr_done = true;
    }

    convert_nat<<<2048, 256>>>(Wx0, bx0, bh0, bx1, bh1);
    convert_frag<<<4096, 256>>>(Wh0, Wx1, Wh1);
    init_kernel<<<1, 32>>>();
    precompute_kernel<<<dim3(G_ / 128, (S_ * B_) / 128), 256>>>(x);
    lstm_persist<<<NCTA, NTHR, SM_TOT>>>(out);
}

// round 6
// speedup vs baseline: 1.7166x; 1.3383x over previous
#include <cuda_runtime.h>
#include <cstdint>

// Problem dims
#define B_  64
#define S_  512
#define I_  512
#define H_  1024
#define G_  4096          // 4*H
#define BH_ (B_*H_)       // 65536
#define OUT_ELEMS (B_*S_*H_)   // 33554432

#define NCTA  128
#define NTHR  544         // 512 consumers + 32 producer warp
#define NCONS 512
#define NCH   16          // K-chunks of 64 per 1024-wide matrix (storage layout)

// persistent-kernel smem plan
// 3 stages x 64KB: [0,32768) B(h), [32768,49152) A0, [49152,65536) A1
// partial-sum buffer overlays stage area after consumption: 8 x 17408B
#define STG_SZ 65536
#define NSTG   3
#define SM_BI  196608
#define SM_MB  196736     // full[3] @ +0, empty[3] @ +24
#define SM_TOT 196800

// ---------------- device scratch (static, allowed) ----------------
__device__ float  g_Wx0p[G_*I_];            // tf32-rounded, gate-permuted rows (for precompute)
__device__ float  g_b0p[G_];                // bx0+bh0, permuted (folded into G0)
__device__ float  g_b1p[G_];                // bx1+bh1, permuted
__device__ float4 g_A0[(size_t)NCTA*NCH*512];  // Wh0 fragment-major
__device__ float4 g_A1[(size_t)NCTA*NCH*512];  // Wx1
__device__ float4 g_A2[(size_t)NCTA*NCH*512];  // Wh1
__device__ float  g_G0[(size_t)S_*B_*G_];   // x-path preactivations [t][b][prow] (512MB)
__device__ float4 g_h0F[2][16384];          // h0 fragment-major, double buffered
__device__ float4 g_h1F[2][16384];          // h1 fragment-major
__device__ unsigned g_barCount;
__device__ volatile unsigned g_barGen;

// ---------------- helpers ----------------
__device__ __forceinline__ float f2tf_f(float f) {
    uint32_t r;
    asm("cvt.rna.tf32.f32 %0, %1;" : "=r"(r) : "f"(f));
    return __uint_as_float(r);
}

__device__ __forceinline__ void mma_tf32(float* d, float4 a, float2 b) {
    asm volatile(
        "mma.sync.aligned.m16n8k8.row.col.f32.tf32.tf32.f32 "
        "{%0,%1,%2,%3}, {%4,%5,%6,%7}, {%8,%9}, {%0,%1,%2,%3};\n"
        : "+f"(d[0]), "+f"(d[1]), "+f"(d[2]), "+f"(d[3])
        : "r"(__float_as_uint(a.x)), "r"(__float_as_uint(a.y)),
          "r"(__float_as_uint(a.z)), "r"(__float_as_uint(a.w)),
          "r"(__float_as_uint(b.x)), "r"(__float_as_uint(b.y)));
}

__device__ __forceinline__ float sigmoidf_(float x) { return 1.0f / (1.0f + expf(-x)); }

// ---- TMA bulk + mbarrier machinery ----
__device__ __forceinline__ void mbar_init(uint32_t addr, uint32_t count) {
    asm volatile("mbarrier.init.shared.b64 [%0], %1;" :: "r"(addr), "r"(count) : "memory");
}
__device__ __forceinline__ void mbar_expect_tx(uint32_t addr, uint32_t bytes) {
    asm volatile("mbarrier.arrive.expect_tx.shared.b64 _, [%0], %1;"
                 :: "r"(addr), "r"(bytes) : "memory");
}
__device__ __forceinline__ void mbar_arrive(uint32_t addr) {
    asm volatile("mbarrier.arrive.shared.b64 _, [%0];" :: "r"(addr) : "memory");
}
__device__ __forceinline__ void bulk_g2s(uint32_t dst, const void* src,
                                         uint32_t bytes, uint32_t mbar) {
    asm volatile(
        "cp.async.bulk.shared::cta.global.mbarrier::complete_tx::bytes [%0], [%1], %2, [%3];"
        :: "r"(dst), "l"(src), "r"(bytes), "r"(mbar) : "memory");
}
__device__ __forceinline__ void mbar_wait(uint32_t mbar, uint32_t parity) {
    asm volatile(
        "{\n\t"
        ".reg .pred P;\n\t"
        "WAIT_LOOP_%=:\n\t"
        "mbarrier.try_wait.parity.acquire.cta.shared::cta.b64 P, [%0], %1, 0x989680;\n\t"
        "@P bra.uni WAIT_DONE_%=;\n\t"
        "bra.uni WAIT_LOOP_%=;\n\t"
        "WAIT_DONE_%=:\n\t"
        "}"
        :: "r"(mbar), "r"(parity) : "memory");
}

// grid barrier (all NCTA CTAs co-resident)
__device__ __forceinline__ void gsync() {
    __syncthreads();
    if (threadIdx.x == 0) {
        unsigned gen = g_barGen;
        __threadfence();
        if (atomicAdd(&g_barCount, 1u) == NCTA - 1) {
            g_barCount = 0;
            __threadfence();
            g_barGen = gen + 1;
        } else {
            while (g_barGen == gen) { }
            __threadfence();
        }
    }
    __syncthreads();
}

// Row permutation: prow = (u/8)*32 + q*8 + (u%8); CTA c owns units [8c,8c+8).

// ---------------- convert: natural Wx0 + biases ----------------
__global__ void __launch_bounds__(256) convert_nat(
    const float* __restrict__ Wx0, const float* __restrict__ bx0, const float* __restrict__ bh0,
    const float* __restrict__ bx1, const float* __restrict__ bh1)
{
    const int total = G_ * I_;
    for (int i = blockIdx.x * blockDim.x + threadIdx.x; i < total;
         i += gridDim.x * blockDim.x) {
        int prow = i / I_;
        int k    = i - prow * I_;
        int u    = ((prow >> 5) << 3) + (prow & 7);
        int q    = (prow >> 3) & 3;
        int orig = q * H_ + u;
        g_Wx0p[i] = f2tf_f(Wx0[(size_t)orig * I_ + k]);
        if (k == 0) {
            g_b0p[prow] = bx0[orig] + bh0[orig];
            g_b1p[prow] = bx1[orig] + bh1[orig];
        }
    }
}

// ---------------- convert: fragment-major recurrent weights ----------------
__global__ void __launch_bounds__(256) convert_frag(
    const float* __restrict__ Wh0, const float* __restrict__ Wx1, const float* __restrict__ Wh1)
{
    const int total = NCTA * NCH * 512;
    for (int idx = blockIdx.x * blockDim.x + threadIdx.x; idx < total;
         idx += gridDim.x * blockDim.x) {
        int lane = idx & 31;
        int kk   = (idx >> 5) & 7;
        int wm   = (idx >> 8) & 1;
        int ch   = (idx >> 9) & 15;
        int c    = idx >> 13;
        int g4 = lane >> 2, t4 = lane & 3;
        int p0 = wm * 16 + g4;
        int q0 = p0 >> 3, v = p0 & 7;
        int o0 = q0 * H_ + c * 8 + v;
        int k  = ch * 64 + kk * 8 + t4;
        size_t r0 = (size_t)o0 * H_ + k;
        size_t r1 = r0 + (size_t)H_ * H_;
        g_A0[idx] = make_float4(f2tf_f(Wh0[r0]), f2tf_f(Wh0[r1]),
                                f2tf_f(Wh0[r0 + 4]), f2tf_f(Wh0[r1 + 4]));
        g_A1[idx] = make_float4(f2tf_f(Wx1[r0]), f2tf_f(Wx1[r1]),
                                f2tf_f(Wx1[r0 + 4]), f2tf_f(Wx1[r1 + 4]));
        g_A2[idx] = make_float4(f2tf_f(Wh1[r0]), f2tf_f(Wh1[r1]),
                                f2tf_f(Wh1[r0 + 4]), f2tf_f(Wh1[r1 + 4]));
    }
}

// ---------------- init (every replay): barrier state only ----------------
__global__ void init_kernel() {
    if (threadIdx.x == 0) { g_barCount = 0; g_barGen = 0; }
}

// ---------------- x-path precompute: G0 = x@Wx0p^T + b0p ----------------
__global__ void __launch_bounds__(256, 1) precompute_kernel(const float* __restrict__ x)
{
    __shared__ float As[128][20];
    __shared__ float Bs[128][20];

    const int tid  = threadIdx.x;
    const int w    = tid >> 5;
    const int lane = tid & 31;
    const int wM   = w >> 2;
    const int wN   = w & 3;
    const int mBase = blockIdx.y * 128;
    const int nBase = blockIdx.x * 128;
    const int g4 = lane >> 2;
    const int t4 = lane & 3;

    float acc[4][4][4];
#pragma unroll
    for (int mt = 0; mt < 4; mt++)
#pragma unroll
        for (int nt = 0; nt < 4; nt++)
#pragma unroll
            for (int e = 0; e < 4; e++) acc[mt][nt][e] = 0.0f;

    for (int kc = 0; kc < I_; kc += 16) {
#pragma unroll
        for (int it = 0; it < 2; it++) {
            int i  = tid + it * 256;
            int r  = i >> 2;
            int c4 = (i & 3) * 4;
            int m  = mBase + r;
            int tt = m >> 6;
            int bb = m & 63;
            float4 v = *(const float4*)(x + ((size_t)bb * S_ + tt) * I_ + kc + c4);
            As[r][c4 + 0] = f2tf_f(v.x); As[r][c4 + 1] = f2tf_f(v.y);
            As[r][c4 + 2] = f2tf_f(v.z); As[r][c4 + 3] = f2tf_f(v.w);
        }
#pragma unroll
        for (int it = 0; it < 2; it++) {
            int i  = tid + it * 256;
            int r  = i >> 2;
            int c4 = (i & 3) * 4;
            float4 v = *(const float4*)(g_Wx0p + (size_t)(nBase + r) * I_ + kc + c4);
            Bs[r][c4 + 0] = v.x; Bs[r][c4 + 1] = v.y;
            Bs[r][c4 + 2] = v.z; Bs[r][c4 + 3] = v.w;
        }
        __syncthreads();

#pragma unroll
        for (int kk = 0; kk < 2; kk++) {
            int k = kk * 8;
            float2 bf[4];
#pragma unroll
            for (int nt = 0; nt < 4; nt++) {
                int n = wN * 32 + nt * 8 + g4;
                bf[nt] = make_float2(Bs[n][k + t4], Bs[n][k + t4 + 4]);
            }
#pragma unroll
            for (int mt = 0; mt < 4; mt++) {
                int r = wM * 64 + mt * 16 + g4;
                float4 af = make_float4(As[r][k + t4], As[r + 8][k + t4],
                                        As[r][k + t4 + 4], As[r + 8][k + t4 + 4]);
#pragma unroll
                for (int nt = 0; nt < 4; nt++)
                    mma_tf32(acc[mt][nt], af, bf[nt]);
            }
        }
        __syncthreads();
    }

#pragma unroll
    for (int mt = 0; mt < 4; mt++) {
        int r0 = mBase + wM * 64 + mt * 16 + g4;
        int r1 = r0 + 8;
#pragma unroll
        for (int nt = 0; nt < 4; nt++) {
            int n0 = nBase + wN * 32 + nt * 8 + t4 * 2;
            float2 bv = *(const float2*)(g_b0p + n0);
            *(float2*)(g_G0 + (size_t)r0 * G_ + n0) =
                make_float2(acc[mt][nt][0] + bv.x, acc[mt][nt][1] + bv.y);
            *(float2*)(g_G0 + (size_t)r1 * G_ + n0) =
                make_float2(acc[mt][nt][2] + bv.x, acc[mt][nt][3] + bv.y);
        }
    }
}

// ---------------- persistent recurrent kernel (producer/consumer, max-reuse tiling) ----
// Consumer warps 0..15: ks = w&7 (K-eighth), wm = w>>3 (prow half), full N=64.
// Producer warp 16 (tid 512): issues TMA for 16 K=128 chunks/step into 3 stages.
// Chunks 0..7: {B=h0, A0=Wh0, A1=Wx1}; chunks 8..15: {B=h1, A0slot=Wh1}.
// Stage-use parities are closed-form in (t, ch): uses/step = {6,5,5} per stage.

__global__ void __launch_bounds__(NTHR, 1) lstm_persist(float* __restrict__ out)
{
    extern __shared__ char sm[];
    float* sB = (float*)(sm + SM_BI);
    float* P  = (float*)sm;                       // partial buffer (overlay)
    const uint32_t smBase = (uint32_t)__cvta_generic_to_shared(sm);
    const uint32_t fullB  = smBase + SM_MB;
    const uint32_t emptyB = smBase + SM_MB + 24;

    const int c    = blockIdx.x;
    const int tid  = threadIdx.x;
    const int w    = tid >> 5;
    const int lane = tid & 31;
    const int ks   = w & 7;          // consumer K-eighth
    const int wm   = (w >> 3) & 1;   // prow half
    const int g4   = lane >> 2;
    const int t4   = lane & 3;
    const int v    = tid & 7;        // unit within CTA (consumers)
    const int b    = tid >> 3;       // batch (consumers, <64)
    const int u    = c * 8 + v;
    const int fidx = ((c * 256 + ((b >> 3) * 4 + (v & 3)) * 8 + (b & 7)) << 1) + (v >> 2);

    if (tid == 0) {
#pragma unroll
        for (int s = 0; s < NSTG; s++) {
            mbar_init(fullB  + s * 8, 1);
            mbar_init(emptyB + s * 8, 16);
        }
    }
    if (tid < 32) sB[tid] = g_b1p[c * 32 + tid];
    asm volatile("fence.proxy.async.shared::cta;" ::: "memory");
    __syncthreads();

    float c0r = 0.f, c1r = 0.f;

    // preamble: h0[0] from G0[0] (h=0), zero h1[-1] fragments
    if (tid < NCONS) {
        float* h0w0 = (float*)g_h0F[0];
        float* h1w0 = (float*)g_h1F[0];
        size_t gbase = (size_t)b * G_ + c * 32;
        float gi = g_G0[gbase + v];
        float go = g_G0[gbase + 16 + v];
        float gg = g_G0[gbase + 24 + v];
        float cn = sigmoidf_(gi) * tanhf(gg);
        float hn = sigmoidf_(go) * tanhf(cn);
        c0r = cn;
        h0w0[fidx] = f2tf_f(hn);
        h1w0[fidx] = 0.f;
    }
    gsync();

    const float4* a0B = g_A0 + (size_t)c * (NCH * 512);
    const float4* a1B = g_A1 + (size_t)c * (NCH * 512);
    const float4* a2B = g_A2 + (size_t)c * (NCH * 512);

    for (int t = 0; t < S_; t++) {
        const float4* bH0 = g_h0F[t & 1];          // h0[t]
        float*        wH0 = (float*)g_h0F[(t + 1) & 1];
        const float4* bH1 = g_h1F[t & 1];          // h1[t-1]
        float*        wH1 = (float*)g_h1F[(t + 1) & 1];

        // consumers: prefetch next layer0's G0 operands
        float p_gi = 0.f, p_gf = 0.f, p_go = 0.f, p_gg = 0.f;
        if (tid < NCONS && t + 1 < S_) {
            size_t gb = ((size_t)(t + 1) * B_ + b) * G_ + c * 32;
            p_gi = g_G0[gb + v];
            p_gf = g_G0[gb + 8 + v];
            p_go = g_G0[gb + 16 + v];
            p_gg = g_G0[gb + 24 + v];
        }

        float acc0[8][4], acc1[8][4];
#pragma unroll
        for (int bt = 0; bt < 8; bt++)
#pragma unroll
            for (int e = 0; e < 4; e++) { acc0[bt][e] = 0.f; acc1[bt][e] = 0.f; }

        if (tid == NCONS) {
            // ---------------- producer ----------------
            for (int ch = 0; ch < 16; ch++) {
                int s = ch % 3, n = ch / 3;
                if (t > 0 || ch >= 3) {
                    uint32_t par = (uint32_t)((((s != 0) ? (t & 1) : 0) + n + 1) & 1);
                    mbar_wait(emptyB + s * 8, par);
                }
                uint32_t sb = smBase + (uint32_t)s * STG_SZ;
                uint32_t fb = fullB + s * 8;
                if (ch < 8) {
                    mbar_expect_tx(fb, 65536u);
                    bulk_g2s(sb,          bH0 + (size_t)ch * 2048, 32768, fb);
                    bulk_g2s(sb + 32768,  a0B + (size_t)ch * 1024, 16384, fb);
                    bulk_g2s(sb + 49152,  a1B + (size_t)ch * 1024, 16384, fb);
                } else {
                    int cc = ch - 8;
                    mbar_expect_tx(fb, 49152u);
                    bulk_g2s(sb,          bH1 + (size_t)cc * 2048, 32768, fb);
                    bulk_g2s(sb + 32768,  a2B + (size_t)cc * 1024, 16384, fb);
                }
            }
        } else if (tid < NCONS) {
            // ---------------- consumers ----------------
            // chunks 0..7 : Wh0 -> acc0, Wx1 -> acc1  (B = h0[t])
            for (int ch = 0; ch < 8; ch++) {
                int s = ch % 3, n = ch / 3;
                uint32_t par = (uint32_t)((((s != 0) ? (t & 1) : 0) + n) & 1);
                mbar_wait(fullB + s * 8, par);
                const char* st = sm + s * STG_SZ;
                const float4* A0f = (const float4*)(st + 32768);
                const float4* A1f = (const float4*)(st + 49152);
#pragma unroll
                for (int half = 0; half < 2; half++) {
                    int aidx = half * 512 + (wm * 8 + ks) * 32 + lane;
                    float4 a0 = A0f[aidx];
                    float4 a1 = A1f[aidx];
                    const char* bb = st + (ks + half * 8) * 2048 + t4 * 64 + g4 * 8;
#pragma unroll
                    for (int bt = 0; bt < 8; bt++) {
                        float2 bf = *(const float2*)(bb + bt * 256);
                        mma_tf32(acc0[bt], a0, bf);
                        mma_tf32(acc1[bt], a1, bf);
                    }
                }
                if (lane == 0) mbar_arrive(emptyB + s * 8);
            }
            // chunks 8..15 : Wh1 -> acc1  (B = h1[t-1])
            for (int ch = 8; ch < 16; ch++) {
                int s = ch % 3, n = ch / 3;
                uint32_t par = (uint32_t)((((s != 0) ? (t & 1) : 0) + n) & 1);
                mbar_wait(fullB + s * 8, par);
                const char* st = sm + s * STG_SZ;
                const float4* A0f = (const float4*)(st + 32768);
#pragma unroll
                for (int half = 0; half < 2; half++) {
                    int aidx = half * 512 + (wm * 8 + ks) * 32 + lane;
                    float4 a0 = A0f[aidx];
                    const char* bb = st + (ks + half * 8) * 2048 + t4 * 64 + g4 * 8;
#pragma unroll
                    for (int bt = 0; bt < 8; bt++) {
                        float2 bf = *(const float2*)(bb + bt * 256);
                        mma_tf32(acc1[bt], a0, bf);
                    }
                }
                if (lane == 0) mbar_arrive(emptyB + s * 8);
            }
        }
        __syncthreads();   // all stages consumed; safe to overlay partials

        // ---- write K-split partials (row stride 68 floats, 4352 floats per ks) ----
        if (tid < NCONS) {
            int r0 = wm * 16 + g4;
            int base0 = ks * 4352;
#pragma unroll
            for (int bt = 0; bt < 8; bt++) {
                int col = bt * 8 + t4 * 2;
                *(float2*)&P[base0 + r0 * 68 + col]        = make_float2(acc0[bt][0], acc0[bt][1]);
                *(float2*)&P[base0 + (r0 + 8) * 68 + col]  = make_float2(acc0[bt][2], acc0[bt][3]);
                *(float2*)&P[base0 + 2176 + r0 * 68 + col]       = make_float2(acc1[bt][0], acc1[bt][1]);
                *(float2*)&P[base0 + 2176 + (r0 + 8) * 68 + col] = make_float2(acc1[bt][2], acc1[bt][3]);
            }
        }
        __syncthreads();

        // ---- reduce 8 partials + cell epilogues ----
        if (tid < NCONS) {
            float g0[4], g1[4];
#pragma unroll
            for (int q = 0; q < 4; q++) {
                int row = q * 8 + v;
                float s0 = 0.f, s1 = 0.f;
#pragma unroll
                for (int kr = 0; kr < 8; kr++) {
                    s0 += P[kr * 4352 + row * 68 + b];
                    s1 += P[kr * 4352 + 2176 + row * 68 + b];
                }
                g0[q] = s0; g1[q] = s1;
            }
            // layer 1 step t
            {
                float gi = g1[0] + sB[v];
                float gf = g1[1] + sB[8 + v];
                float go = g1[2] + sB[16 + v];
                float gg = g1[3] + sB[24 + v];
                float cn = sigmoidf_(gf) * c1r + sigmoidf_(gi) * tanhf(gg);
                float hn = sigmoidf_(go) * tanhf(cn);
                c1r = cn;
                out[((size_t)b * S_ + t) * H_ + u] = hn;
                wH1[fidx] = f2tf_f(hn);
                if (t == S_ - 1) {
                    out[(size_t)OUT_ELEMS + 1ull * BH_ + (size_t)b * H_ + u] = hn;
                    out[(size_t)OUT_ELEMS + 3ull * BH_ + (size_t)b * H_ + u] = cn;
                }
            }
            // layer 0 step t+1
            if (t < S_ - 1) {
                float gi = g0[0] + p_gi;
                float gf = g0[1] + p_gf;
                float go = g0[2] + p_go;
                float gg = g0[3] + p_gg;
                float cn = sigmoidf_(gf) * c0r + sigmoidf_(gi) * tanhf(gg);
                float hn = sigmoidf_(go) * tanhf(cn);
                c0r = cn;
                wH0[fidx] = f2tf_f(hn);
                if (t == S_ - 2) {
                    out[(size_t)OUT_ELEMS + (size_t)b * H_ + u]              = hn;
                    out[(size_t)OUT_ELEMS + 2ull * BH_ + (size_t)b * H_ + u] = cn;
                }
            }
        }
        if (t + 1 < S_) gsync();
    }
}

// ---------------- launch ----------------
extern "C" void kernel_launch(void* const* d_in, const int* in_sizes, int n_in,
                              void* d_out, int out_size)
{
    const float* x   = (const float*)d_in[0];
    const float* Wx0 = (const float*)d_in[1];
    const float* Wh0 = (const float*)d_in[2];
    const float* bx0 = (const float*)d_in[3];
    const float* bh0 = (const float*)d_in[4];
    const float* Wx1 = (const float*)d_in[5];
    const float* Wh1 = (const float*)d_in[6];
    const float* bx1 = (const float*)d_in[7];
    const float* bh1 = (const float*)d_in[8];
    float* out = (float*)d_out;

    static bool attr_done = false;
    if (!attr_done) {
        cudaFuncSetAttribute(lstm_persist,
                             cudaFuncAttributeMaxDynamicSharedMemorySize, SM_TOT);
        attr_done = true;
    }

    convert_nat<<<2048, 256>>>(Wx0, bx0, bh0, bx1, bh1);
    convert_frag<<<4096, 256>>>(Wh0, Wx1, Wh1);
    init_kernel<<<1, 32>>>();
    precompute_kernel<<<dim3(G_ / 128, (S_ * B_) / 128), 256>>>(x);
    lstm_persist<<<NCTA, NTHR, SM_TOT>>>(out);
}